// round 2
// baseline (speedup 1.0000x reference)
#include <cuda_runtime.h>
#include <cuda_bf16.h>
#include <cstdint>

// Problem constants (fixed shapes from reference)
#define TOKENS   131072      // 32 * 4096
#define CDIM     256
#define QKVDIM   768         // 3*C
#define NWIN     16384       // TOKENS / 8
#define NHEAD    4
#define HDIM     64

// Scratch: device globals (no runtime allocation allowed)
__device__ float g_qkv[(size_t)TOKENS * QKVDIM];   // [tokens, 768]
__device__ float g_att[(size_t)TOKENS * CDIM];     // [tokens, 256]

// ----------------------------------------------------------------------------
// Tiled fp32 GEMM: C[M,N] = A[M,K] @ B[N,K]^T + bias[N]
// BM=BN=128, BK=16, 256 threads, 8x8 per-thread tile, float4 smem fragments.
// Assumes M%128==0, N%128==0, K%16==0, all pointers 16B-aligned.
// ----------------------------------------------------------------------------
#define BM 128
#define BN 128
#define BKT 16
#define TM 8
#define TN 8

__global__ __launch_bounds__(256, 2) void gemm_abt_bias(
    const float* __restrict__ A, const float* __restrict__ B,
    const float* __restrict__ bias, float* __restrict__ C,
    int M, int N, int K)
{
    __shared__ float As[BKT][BM];
    __shared__ float Bs[BKT][BN];

    const int tid  = threadIdx.x;
    const int brow = blockIdx.y * BM;
    const int bcol = blockIdx.x * BN;
    const int tx = tid & 15;   // 0..15 (col group)
    const int ty = tid >> 4;   // 0..15 (row group)

    float acc[TM][TN];
    #pragma unroll
    for (int i = 0; i < TM; i++)
        #pragma unroll
        for (int j = 0; j < TN; j++) acc[i][j] = 0.0f;

    for (int kk = 0; kk < K; kk += BKT) {
        // Each tile is 128x16 floats = 512 float4; 256 threads -> 2 float4 each per tile.
        #pragma unroll
        for (int r = 0; r < 2; r++) {
            int id  = tid + r * 256;        // 0..511
            int row = id >> 2;              // 0..127
            int k4  = (id & 3) << 2;        // 0,4,8,12
            float4 av = *reinterpret_cast<const float4*>(
                &A[(size_t)(brow + row) * K + kk + k4]);
            As[k4 + 0][row] = av.x; As[k4 + 1][row] = av.y;
            As[k4 + 2][row] = av.z; As[k4 + 3][row] = av.w;
            float4 bv = *reinterpret_cast<const float4*>(
                &B[(size_t)(bcol + row) * K + kk + k4]);
            Bs[k4 + 0][row] = bv.x; Bs[k4 + 1][row] = bv.y;
            Bs[k4 + 2][row] = bv.z; Bs[k4 + 3][row] = bv.w;
        }
        __syncthreads();

        #pragma unroll
        for (int k = 0; k < BKT; k++) {
            float a_frag[TM], b_frag[TN];
            #pragma unroll
            for (int i = 0; i < TM; i += 4)
                *reinterpret_cast<float4*>(&a_frag[i]) =
                    *reinterpret_cast<const float4*>(&As[k][ty * TM + i]);
            #pragma unroll
            for (int j = 0; j < TN; j += 4)
                *reinterpret_cast<float4*>(&b_frag[j]) =
                    *reinterpret_cast<const float4*>(&Bs[k][tx * TN + j]);
            #pragma unroll
            for (int i = 0; i < TM; i++)
                #pragma unroll
                for (int j = 0; j < TN; j++)
                    acc[i][j] = fmaf(a_frag[i], b_frag[j], acc[i][j]);
        }
        __syncthreads();
    }

    #pragma unroll
    for (int i = 0; i < TM; i++) {
        int row = brow + ty * TM + i;
        #pragma unroll
        for (int j = 0; j < TN; j += 4) {
            int col = bcol + tx * TN + j;
            float4 o;
            o.x = acc[i][j + 0] + bias[col + 0];
            o.y = acc[i][j + 1] + bias[col + 1];
            o.z = acc[i][j + 2] + bias[col + 2];
            o.w = acc[i][j + 3] + bias[col + 3];
            *reinterpret_cast<float4*>(&C[(size_t)row * N + col]) = o;
        }
    }
}

// ----------------------------------------------------------------------------
// Windowed causal attention: one warp per (window, head).
// qkv layout: [token, 768] with cols [0:256)=Q, [256:512)=K, [512:768)=V,
// each arranged head-major (h*64 + d). Output att: [token, 256], c = h*64+d.
// ----------------------------------------------------------------------------
__global__ __launch_bounds__(256) void attn_window_kernel(
    const float* __restrict__ qkv, float* __restrict__ att_out)
{
    const int warp_global = blockIdx.x * 8 + (threadIdx.x >> 5);
    const int lane = threadIdx.x & 31;
    const int win = warp_global >> 2;       // / NHEAD
    const int h   = warp_global & 3;        // % NHEAD
    const float scale = 0.125f;             // hd^-0.5 = 1/8

    const float* base = qkv + (size_t)win * 8 * QKVDIM + h * HDIM;

    // Each lane holds 2 of the 64 head-dims: d = ld*32 + lane
    float q[8][2], k[8][2], v[8][2];
    #pragma unroll
    for (int i = 0; i < 8; i++) {
        #pragma unroll
        for (int ld = 0; ld < 2; ld++) {
            int d = ld * 32 + lane;
            q[i][ld] = base[i * QKVDIM + d];
            k[i][ld] = base[i * QKVDIM + 256 + d];
            v[i][ld] = base[i * QKVDIM + 512 + d];
        }
    }

    // Scores via butterfly reduction -> every lane holds the full 8x8 matrix
    float p[8][8];
    #pragma unroll
    for (int i = 0; i < 8; i++) {
        #pragma unroll
        for (int j = 0; j < 8; j++) {
            float s = q[i][0] * k[j][0] + q[i][1] * k[j][1];
            #pragma unroll
            for (int o = 16; o > 0; o >>= 1)
                s += __shfl_xor_sync(0xffffffffu, s, o);
            p[i][j] = s * scale;
        }
    }

    // Causal softmax per row (all lanes redundantly; data already broadcast)
    #pragma unroll
    for (int i = 0; i < 8; i++) {
        float mx = p[i][0];
        #pragma unroll
        for (int j = 1; j < 8; j++)
            if (j <= i) mx = fmaxf(mx, p[i][j]);
        float sum = 0.0f;
        #pragma unroll
        for (int j = 0; j < 8; j++) {
            if (j <= i) { float e = __expf(p[i][j] - mx); p[i][j] = e; sum += e; }
            else          p[i][j] = 0.0f;
        }
        float inv = 1.0f / sum;
        #pragma unroll
        for (int j = 0; j < 8; j++) p[i][j] *= inv;
    }

    // out[i][d] = sum_j p[i][j] * v[j][d]
    float* obase = att_out + (size_t)win * 8 * CDIM + h * HDIM;
    #pragma unroll
    for (int i = 0; i < 8; i++) {
        #pragma unroll
        for (int ld = 0; ld < 2; ld++) {
            float acc = 0.0f;
            #pragma unroll
            for (int j = 0; j < 8; j++)
                acc = fmaf(p[i][j], v[j][ld], acc);
            obase[i * CDIM + ld * 32 + lane] = acc;
        }
    }
}

// ----------------------------------------------------------------------------
// Launch: QKV GEMM -> windowed attention -> proj GEMM (same stream, serialized)
// ----------------------------------------------------------------------------
extern "C" void kernel_launch(void* const* d_in, const int* in_sizes, int n_in,
                              void* d_out, int out_size)
{
    const float* x      = (const float*)d_in[0];
    const float* w_qkv  = (const float*)d_in[1];
    const float* b_qkv  = (const float*)d_in[2];
    const float* w_proj = (const float*)d_in[3];
    const float* b_proj = (const float*)d_in[4];
    float* out = (float*)d_out;

    float* qkv_buf = nullptr;
    float* att_buf = nullptr;
    cudaGetSymbolAddress((void**)&qkv_buf, g_qkv);
    cudaGetSymbolAddress((void**)&att_buf, g_att);

    // K1: qkv = x @ w_qkv^T + b_qkv   (M=131072, N=768, K=256)
    {
        dim3 grid(QKVDIM / BN, TOKENS / BM);
        gemm_abt_bias<<<grid, 256>>>(x, w_qkv, b_qkv, qkv_buf,
                                     TOKENS, QKVDIM, CDIM);
    }

    // K2: windowed causal attention (65536 warps, 8 warps per block)
    {
        int nwarps = NWIN * NHEAD;
        attn_window_kernel<<<nwarps / 8, 256>>>(qkv_buf, att_buf);
    }

    // K3: out = att @ w_proj^T + b_proj  (M=131072, N=256, K=256)
    {
        dim3 grid(CDIM / BN, TOKENS / BM);
        gemm_abt_bias<<<grid, 256>>>(att_buf, w_proj, b_proj, out,
                                     TOKENS, CDIM, CDIM);
    }
}

// round 8
// speedup vs baseline: 3.8557x; 3.8557x over previous
#include <cuda_runtime.h>
#include <cuda_bf16.h>
#include <cstdint>

// ---------------------------------------------------------------------------
// Problem constants
// ---------------------------------------------------------------------------
#define TOKENS   131072      // 32 * 4096
#define CDIM     256
#define QKVDIM   768
#define NWIN     16384
#define NHEAD    4
#define HDIM     64

// ---------------------------------------------------------------------------
// Scratch (device globals — no runtime allocation allowed)
// ---------------------------------------------------------------------------
__device__ float g_qkv[(size_t)TOKENS * QKVDIM];  // fp32 qkv
__device__ __align__(16) __nv_bfloat16 g_xh [(size_t)TOKENS * CDIM];
__device__ __align__(16) __nv_bfloat16 g_xl [(size_t)TOKENS * CDIM];
__device__ __align__(16) __nv_bfloat16 g_ath[(size_t)TOKENS * CDIM];
__device__ __align__(16) __nv_bfloat16 g_atl[(size_t)TOKENS * CDIM];
__device__ __align__(16) __nv_bfloat16 g_wqh[(size_t)QKVDIM * CDIM];
__device__ __align__(16) __nv_bfloat16 g_wql[(size_t)QKVDIM * CDIM];
__device__ __align__(16) __nv_bfloat16 g_wph[(size_t)CDIM * CDIM];
__device__ __align__(16) __nv_bfloat16 g_wpl[(size_t)CDIM * CDIM];

// ---------------------------------------------------------------------------
// Low-level helpers (sm_80-era ISA only: ldmatrix / mma.sync / cp.async)
// ---------------------------------------------------------------------------
__device__ __forceinline__ uint32_t smem_to_u32(const void* p) {
    uint32_t a;
    asm("{ .reg .u64 t; cvta.to.shared.u64 t, %1; cvt.u32.u64 %0, t; }"
        : "=r"(a) : "l"(p));
    return a;
}

__device__ __forceinline__ void cp_async16(uint32_t dst, const void* src) {
    asm volatile("cp.async.cg.shared.global [%0], [%1], 16;"
                 :: "r"(dst), "l"(src));
}
__device__ __forceinline__ void cp_commit() {
    asm volatile("cp.async.commit_group;");
}
template <int N>
__device__ __forceinline__ void cp_wait() {
    asm volatile("cp.async.wait_group %0;" :: "n"(N));
}

__device__ __forceinline__ void ldmx4(uint32_t* r, uint32_t addr) {
    asm volatile("ldmatrix.sync.aligned.m8n8.x4.shared.b16 {%0,%1,%2,%3}, [%4];"
                 : "=r"(r[0]), "=r"(r[1]), "=r"(r[2]), "=r"(r[3]) : "r"(addr));
}

__device__ __forceinline__ void mma_bf16(float* d, const uint32_t* a,
                                         uint32_t b0, uint32_t b1) {
    asm volatile(
        "mma.sync.aligned.m16n8k16.row.col.f32.bf16.bf16.f32 "
        "{%0,%1,%2,%3}, {%4,%5,%6,%7}, {%8,%9}, {%0,%1,%2,%3};"
        : "+f"(d[0]), "+f"(d[1]), "+f"(d[2]), "+f"(d[3])
        : "r"(a[0]), "r"(a[1]), "r"(a[2]), "r"(a[3]), "r"(b0), "r"(b1));
}

#define SMEM_SWIZZLE_128B(off) ((off) ^ (((off) >> 3) & 0x70))

// ---------------------------------------------------------------------------
// Split-convert: fp32 -> (hi, lo) bf16 pair (error-free 2-term split)
// ---------------------------------------------------------------------------
__global__ __launch_bounds__(256) void convert_split(
    const float* __restrict__ src,
    __nv_bfloat16* __restrict__ hi, __nv_bfloat16* __restrict__ lo, int n4)
{
    int i = blockIdx.x * blockDim.x + threadIdx.x;
    if (i >= n4) return;
    float4 v = reinterpret_cast<const float4*>(src)[i];
    float f[4] = {v.x, v.y, v.z, v.w};
    __nv_bfloat16 h[4], l[4];
    #pragma unroll
    for (int j = 0; j < 4; j++) {
        h[j] = __float2bfloat16(f[j]);
        l[j] = __float2bfloat16(f[j] - __bfloat162float(h[j]));
    }
    __nv_bfloat162* ph = reinterpret_cast<__nv_bfloat162*>(hi + (size_t)i * 4);
    __nv_bfloat162* pl = reinterpret_cast<__nv_bfloat162*>(lo + (size_t)i * 4);
    ph[0] = __halves2bfloat162(h[0], h[1]);
    ph[1] = __halves2bfloat162(h[2], h[3]);
    pl[0] = __halves2bfloat162(l[0], l[1]);
    pl[1] = __halves2bfloat162(l[2], l[3]);
}

// ---------------------------------------------------------------------------
// HMMA GEMM: C[M,Ntot] = (Ah+Al)[M,256] @ (Bh+Bl)[Ntot,256]^T + bias
// CTA 128x128, 8 warps (2x4), warp tile 64x32, mma.m16n8k16 bf16.
// K-tiles of 64 (128B SW128-swizzled rows), cp.async double-buffered.
// 3-term split: Ah*Bh + Ah*Bl + Al*Bh accumulated in fp32.
// ---------------------------------------------------------------------------
#define BM 128
#define BN 128
#define KT 64
#define NKT 4                        // 256 / 64
#define BUF_BYTES   16384            // 128 rows * 128 B
#define STAGE_BYTES (4 * BUF_BYTES)  // Ah, Al, Bh, Bl
#define GEMM_SMEM   (2 * STAGE_BYTES)

static __device__ __forceinline__ void stage_load(
    uint32_t su, int stage, int tid, int t,
    const __nv_bfloat16* __restrict__ aH, const __nv_bfloat16* __restrict__ aL,
    const __nv_bfloat16* __restrict__ bH, const __nv_bfloat16* __restrict__ bL)
{
    const __nv_bfloat16* srcs[4] = {aH + t * KT, aL + t * KT,
                                    bH + t * KT, bL + t * KT};
    #pragma unroll
    for (int b = 0; b < 4; b++) {
        const __nv_bfloat16* s = srcs[b];
        uint32_t dbase = su + stage * STAGE_BYTES + b * BUF_BYTES;
        #pragma unroll
        for (int i = 0; i < 4; i++) {
            int id  = tid + i * 256;          // 0..1023
            int row = id >> 3, ch = id & 7;   // 128 rows x 8 16B chunks
            uint32_t off = SMEM_SWIZZLE_128B((uint32_t)(row * 128 + ch * 16));
            cp_async16(dbase + off, s + (size_t)row * CDIM + ch * 8);
        }
    }
}

__global__ __launch_bounds__(256, 1) void gemm_tc(
    const __nv_bfloat16* __restrict__ Ah, const __nv_bfloat16* __restrict__ Al,
    const __nv_bfloat16* __restrict__ Bh, const __nv_bfloat16* __restrict__ Bl,
    const float* __restrict__ bias, float* __restrict__ C, int Ntot)
{
    extern __shared__ __align__(128) char sb[];
    const uint32_t su = smem_to_u32(sb);

    const int tid    = threadIdx.x;
    const int wid    = tid >> 5;
    const int lane   = tid & 31;
    const int warp_m = wid >> 2;     // 0..1 -> 64-row slab
    const int warp_n = wid & 3;      // 0..3 -> 32-col slab
    const int brow   = blockIdx.y * BM;
    const int bcol   = blockIdx.x * BN;

    const __nv_bfloat16* aH = Ah + (size_t)brow * CDIM;
    const __nv_bfloat16* aL = Al + (size_t)brow * CDIM;
    const __nv_bfloat16* bH = Bh + (size_t)bcol * CDIM;
    const __nv_bfloat16* bL = Bl + (size_t)bcol * CDIM;

    // ldmatrix per-lane addressing. The swizzle XOR constant (row&7)<<4 must
    // be applied to the FINAL 16B-chunk index, so fold (ch0 + 2*kk) ^ xor
    // inside the k loop (all constants after unroll). mi/g offsets move by
    // 16 rows = row&7 invariant.
    // A matrices: (m0-7,k0-7),(m8-15,k0-7),(m0-7,k8-15),(m8-15,k8-15)
    const int aRow = warp_m * 64 + (lane & 15);
    const int aCh0 = lane >> 4;              // 0,1
    const uint32_t aXor    = (uint32_t)(aRow & 7);
    const uint32_t aRowOff = (uint32_t)aRow * 128;
    // B matrices: (n0-7,k0-7),(n0-7,k8-15),(n8-15,k0-7),(n8-15,k8-15)
    const int bRow = warp_n * 32 + (lane & 7) + ((lane >> 4) << 3);
    const int bCh0 = (lane >> 3) & 1;        // 0,1
    const uint32_t bXor    = (uint32_t)(bRow & 7);
    const uint32_t bRowOff = (uint32_t)bRow * 128;

    float acc[4][4][4];
    #pragma unroll
    for (int mi = 0; mi < 4; mi++)
        #pragma unroll
        for (int ni = 0; ni < 4; ni++)
            #pragma unroll
            for (int j = 0; j < 4; j++) acc[mi][ni][j] = 0.0f;

    stage_load(su, 0, tid, 0, aH, aL, bH, bL);
    cp_commit();

    for (int t = 0; t < NKT; t++) {
        if (t + 1 < NKT) {
            stage_load(su, (t + 1) & 1, tid, t + 1, aH, aL, bH, bL);
            cp_commit();
            cp_wait<1>();           // tile t landed, t+1 in flight
        } else {
            cp_wait<0>();
        }
        __syncthreads();

        const uint32_t sA  = su + (t & 1) * STAGE_BYTES;
        const uint32_t sAl = sA + BUF_BYTES;
        const uint32_t sB  = sA + 2 * BUF_BYTES;
        const uint32_t sBl = sA + 3 * BUF_BYTES;

        #pragma unroll
        for (int kk = 0; kk < 4; kk++) {       // k16 steps within K-tile
            const uint32_t aOff =
                aRowOff + ((((uint32_t)(aCh0 + 2 * kk)) ^ aXor) << 4);
            const uint32_t bOff =
                bRowOff + ((((uint32_t)(bCh0 + 2 * kk)) ^ bXor) << 4);
            uint32_t ah[4][4], al[4][4], bh[2][4], bl[2][4];
            #pragma unroll
            for (int mi = 0; mi < 4; mi++) {
                ldmx4(ah[mi], sA  + aOff + mi * 2048);
                ldmx4(al[mi], sAl + aOff + mi * 2048);
            }
            #pragma unroll
            for (int g = 0; g < 2; g++) {      // n16 groups
                ldmx4(bh[g], sB  + bOff + g * 2048);
                ldmx4(bl[g], sBl + bOff + g * 2048);
            }
            #pragma unroll
            for (int mi = 0; mi < 4; mi++)
                #pragma unroll
                for (int ni = 0; ni < 4; ni++) {
                    const int g = ni >> 1, p = (ni & 1) * 2;
                    mma_bf16(acc[mi][ni], ah[mi], bh[g][p], bh[g][p + 1]);
                    mma_bf16(acc[mi][ni], ah[mi], bl[g][p], bl[g][p + 1]);
                    mma_bf16(acc[mi][ni], al[mi], bh[g][p], bh[g][p + 1]);
                }
        }
        __syncthreads();   // stage (t&1) free for reload at iteration t+1
    }

    // Epilogue: per mma frag, lane l -> rows l/4 & l/4+8, cols (l%4)*2 +{0,1}
    #pragma unroll
    for (int mi = 0; mi < 4; mi++) {
        const int r0 = brow + warp_m * 64 + mi * 16 + (lane >> 2);
        #pragma unroll
        for (int ni = 0; ni < 4; ni++) {
            const int col = bcol + warp_n * 32 + ni * 8 + (lane & 3) * 2;
            const float b0 = bias[col], b1 = bias[col + 1];
            float2 v0 = {acc[mi][ni][0] + b0, acc[mi][ni][1] + b1};
            float2 v1 = {acc[mi][ni][2] + b0, acc[mi][ni][3] + b1};
            *reinterpret_cast<float2*>(&C[(size_t)r0 * Ntot + col]) = v0;
            *reinterpret_cast<float2*>(&C[(size_t)(r0 + 8) * Ntot + col]) = v1;
        }
    }
}

// ---------------------------------------------------------------------------
// Windowed causal attention: one warp per (window, head). Reads fp32 qkv,
// writes bf16 hi/lo split directly (feeds GEMM3 A operand).
// ---------------------------------------------------------------------------
__global__ __launch_bounds__(256) void attn_window_kernel(
    const float* __restrict__ qkv,
    __nv_bfloat16* __restrict__ out_h, __nv_bfloat16* __restrict__ out_l)
{
    const int warp_global = blockIdx.x * 8 + (threadIdx.x >> 5);
    const int lane = threadIdx.x & 31;
    const int win  = warp_global >> 2;
    const int head = warp_global & 3;
    const float scale = 0.125f;

    const float* base = qkv + (size_t)win * 8 * QKVDIM + head * HDIM;

    float q[8][2], k[8][2], v[8][2];
    #pragma unroll
    for (int i = 0; i < 8; i++) {
        #pragma unroll
        for (int ld = 0; ld < 2; ld++) {
            int d = ld * 32 + lane;
            q[i][ld] = base[i * QKVDIM + d];
            k[i][ld] = base[i * QKVDIM + 256 + d];
            v[i][ld] = base[i * QKVDIM + 512 + d];
        }
    }

    float p[8][8];
    #pragma unroll
    for (int i = 0; i < 8; i++) {
        #pragma unroll
        for (int j = 0; j < 8; j++) {
            float s = q[i][0] * k[j][0] + q[i][1] * k[j][1];
            #pragma unroll
            for (int o = 16; o > 0; o >>= 1)
                s += __shfl_xor_sync(0xffffffffu, s, o);
            p[i][j] = s * scale;
        }
    }

    #pragma unroll
    for (int i = 0; i < 8; i++) {
        float mx = p[i][0];
        #pragma unroll
        for (int j = 1; j < 8; j++)
            if (j <= i) mx = fmaxf(mx, p[i][j]);
        float sum = 0.0f;
        #pragma unroll
        for (int j = 0; j < 8; j++) {
            if (j <= i) { float e = __expf(p[i][j] - mx); p[i][j] = e; sum += e; }
            else          p[i][j] = 0.0f;
        }
        float inv = 1.0f / sum;
        #pragma unroll
        for (int j = 0; j < 8; j++) p[i][j] *= inv;
    }

    const size_t obase = (size_t)win * 8 * CDIM + head * HDIM;
    #pragma unroll
    for (int i = 0; i < 8; i++) {
        #pragma unroll
        for (int ld = 0; ld < 2; ld++) {
            float a = 0.0f;
            #pragma unroll
            for (int j = 0; j < 8; j++)
                a = fmaf(p[i][j], v[j][ld], a);
            __nv_bfloat16 hh = __float2bfloat16(a);
            __nv_bfloat16 ll = __float2bfloat16(a - __bfloat162float(hh));
            out_h[obase + i * CDIM + ld * 32 + lane] = hh;
            out_l[obase + i * CDIM + ld * 32 + lane] = ll;
        }
    }
}

// ---------------------------------------------------------------------------
// Launch
// ---------------------------------------------------------------------------
extern "C" void kernel_launch(void* const* d_in, const int* in_sizes, int n_in,
                              void* d_out, int out_size)
{
    const float* x      = (const float*)d_in[0];
    const float* w_qkv  = (const float*)d_in[1];
    const float* b_qkv  = (const float*)d_in[2];
    const float* w_proj = (const float*)d_in[3];
    const float* b_proj = (const float*)d_in[4];
    float* out = (float*)d_out;

    float* qkv_buf;
    __nv_bfloat16 *xh, *xl, *ath, *atl, *wqh, *wql, *wph, *wpl;
    cudaGetSymbolAddress((void**)&qkv_buf, g_qkv);
    cudaGetSymbolAddress((void**)&xh,  g_xh);
    cudaGetSymbolAddress((void**)&xl,  g_xl);
    cudaGetSymbolAddress((void**)&ath, g_ath);
    cudaGetSymbolAddress((void**)&atl, g_atl);
    cudaGetSymbolAddress((void**)&wqh, g_wqh);
    cudaGetSymbolAddress((void**)&wql, g_wql);
    cudaGetSymbolAddress((void**)&wph, g_wph);
    cudaGetSymbolAddress((void**)&wpl, g_wpl);

    cudaFuncSetAttribute(gemm_tc, cudaFuncAttributeMaxDynamicSharedMemorySize,
                         GEMM_SMEM);

    // Split-convert inputs and weights to bf16 hi/lo
    convert_split<<<(TOKENS * CDIM / 4) / 256, 256>>>(x, xh, xl, TOKENS * CDIM / 4);
    convert_split<<<(QKVDIM * CDIM / 4) / 256, 256>>>(w_qkv, wqh, wql, QKVDIM * CDIM / 4);
    convert_split<<<(CDIM * CDIM / 4) / 256, 256>>>(w_proj, wph, wpl, CDIM * CDIM / 4);

    // K1: qkv = x @ w_qkv^T + b_qkv   (M=131072, N=768, K=256)
    {
        dim3 grid(QKVDIM / BN, TOKENS / BM);
        gemm_tc<<<grid, 256, GEMM_SMEM>>>(xh, xl, wqh, wql, b_qkv, qkv_buf, QKVDIM);
    }

    // K2: windowed causal attention -> bf16 hi/lo
    attn_window_kernel<<<(NWIN * NHEAD) / 8, 256>>>(qkv_buf, ath, atl);

    // K3: out = att @ w_proj^T + b_proj  (M=131072, N=256, K=256)
    {
        dim3 grid(CDIM / BN, TOKENS / BM);
        gemm_tc<<<grid, 256, GEMM_SMEM>>>(ath, atl, wph, wpl, b_proj, out, CDIM);
    }
}

// round 10
// speedup vs baseline: 3.9801x; 1.0323x over previous
#include <cuda_runtime.h>
#include <cuda_bf16.h>
#include <cstdint>

// ---------------------------------------------------------------------------
// Problem constants
// ---------------------------------------------------------------------------
#define TOKENS   131072      // 32 * 4096
#define CDIM     256
#define QKVDIM   768
#define NWIN     16384
#define NHEAD    4
#define HDIM     64

// ---------------------------------------------------------------------------
// Scratch (device globals — no runtime allocation allowed)
// ---------------------------------------------------------------------------
__device__ float g_qkv[(size_t)TOKENS * QKVDIM];  // fp32 qkv
__device__ __align__(16) __nv_bfloat16 g_xh [(size_t)TOKENS * CDIM];
__device__ __align__(16) __nv_bfloat16 g_xl [(size_t)TOKENS * CDIM];
__device__ __align__(16) __nv_bfloat16 g_ath[(size_t)TOKENS * CDIM];
__device__ __align__(16) __nv_bfloat16 g_atl[(size_t)TOKENS * CDIM];
__device__ __align__(16) __nv_bfloat16 g_wqh[(size_t)QKVDIM * CDIM];
__device__ __align__(16) __nv_bfloat16 g_wql[(size_t)QKVDIM * CDIM];
__device__ __align__(16) __nv_bfloat16 g_wph[(size_t)CDIM * CDIM];
__device__ __align__(16) __nv_bfloat16 g_wpl[(size_t)CDIM * CDIM];

// ---------------------------------------------------------------------------
// Low-level helpers (sm_80-era ISA only: ldmatrix / mma.sync / cp.async)
// ---------------------------------------------------------------------------
__device__ __forceinline__ uint32_t smem_to_u32(const void* p) {
    uint32_t a;
    asm("{ .reg .u64 t; cvta.to.shared.u64 t, %1; cvt.u32.u64 %0, t; }"
        : "=r"(a) : "l"(p));
    return a;
}

__device__ __forceinline__ void cp_async16(uint32_t dst, const void* src) {
    asm volatile("cp.async.cg.shared.global [%0], [%1], 16;"
                 :: "r"(dst), "l"(src));
}
__device__ __forceinline__ void cp_commit() {
    asm volatile("cp.async.commit_group;");
}
template <int N>
__device__ __forceinline__ void cp_wait() {
    asm volatile("cp.async.wait_group %0;" :: "n"(N));
}

__device__ __forceinline__ void ldmx4(uint32_t* r, uint32_t addr) {
    asm volatile("ldmatrix.sync.aligned.m8n8.x4.shared.b16 {%0,%1,%2,%3}, [%4];"
                 : "=r"(r[0]), "=r"(r[1]), "=r"(r[2]), "=r"(r[3]) : "r"(addr));
}

__device__ __forceinline__ void mma_bf16(float* d, const uint32_t* a,
                                         uint32_t b0, uint32_t b1) {
    asm volatile(
        "mma.sync.aligned.m16n8k16.row.col.f32.bf16.bf16.f32 "
        "{%0,%1,%2,%3}, {%4,%5,%6,%7}, {%8,%9}, {%0,%1,%2,%3};"
        : "+f"(d[0]), "+f"(d[1]), "+f"(d[2]), "+f"(d[3])
        : "r"(a[0]), "r"(a[1]), "r"(a[2]), "r"(a[3]), "r"(b0), "r"(b1));
}

#define SMEM_SWIZZLE_128B(off) ((off) ^ (((off) >> 3) & 0x70))

// ---------------------------------------------------------------------------
// Split-convert: fp32 -> (hi, lo) bf16 pair (error-free 2-term split)
// ---------------------------------------------------------------------------
__global__ __launch_bounds__(256) void convert_split(
    const float* __restrict__ src,
    __nv_bfloat16* __restrict__ hi, __nv_bfloat16* __restrict__ lo, int n4)
{
    int i = blockIdx.x * blockDim.x + threadIdx.x;
    if (i >= n4) return;
    float4 v = reinterpret_cast<const float4*>(src)[i];
    float f[4] = {v.x, v.y, v.z, v.w};
    __nv_bfloat16 h[4], l[4];
    #pragma unroll
    for (int j = 0; j < 4; j++) {
        h[j] = __float2bfloat16(f[j]);
        l[j] = __float2bfloat16(f[j] - __bfloat162float(h[j]));
    }
    __nv_bfloat162* ph = reinterpret_cast<__nv_bfloat162*>(hi + (size_t)i * 4);
    __nv_bfloat162* pl = reinterpret_cast<__nv_bfloat162*>(lo + (size_t)i * 4);
    ph[0] = __halves2bfloat162(h[0], h[1]);
    ph[1] = __halves2bfloat162(h[2], h[3]);
    pl[0] = __halves2bfloat162(l[0], l[1]);
    pl[1] = __halves2bfloat162(l[2], l[3]);
}

// ---------------------------------------------------------------------------
// HMMA GEMM: C[M,Ntot] = (Ah+Al)[M,256] @ (Bh+Bl)[Ntot,256]^T + bias
// CTA 64x128, 8 warps (2m x 4n), warp tile 32x32, mma.m16n8k16 bf16.
// K-tiles of 64 (128B SW128-swizzled rows), cp.async double-buffered.
// 3-term split: Ah*Bh + Ah*Bl + Al*Bh accumulated in fp32.
// Sized for 2 CTAs/SM: 96KB smem, <=128 regs.
// ---------------------------------------------------------------------------
#define BM 64
#define BN 128
#define KT 64
#define NKT 4                        // 256 / 64
#define A_BUF 8192                   // 64 rows * 128 B
#define B_BUF 16384                  // 128 rows * 128 B
#define STAGE_BYTES (2 * A_BUF + 2 * B_BUF)   // Ah, Al, Bh, Bl = 49152
#define GEMM_SMEM   (2 * STAGE_BYTES)         // 98304

static __device__ __forceinline__ void stage_load(
    uint32_t su, int stage, int tid, int t,
    const __nv_bfloat16* __restrict__ aH, const __nv_bfloat16* __restrict__ aL,
    const __nv_bfloat16* __restrict__ bH, const __nv_bfloat16* __restrict__ bL)
{
    const uint32_t sbase = su + stage * STAGE_BYTES;
    // A splits: 64 rows x 8 chunks = 512 cp16 each (2 per thread)
    {
        const __nv_bfloat16* srcs[2] = {aH + t * KT, aL + t * KT};
        #pragma unroll
        for (int b = 0; b < 2; b++) {
            const __nv_bfloat16* s = srcs[b];
            uint32_t dbase = sbase + b * A_BUF;
            #pragma unroll
            for (int i = 0; i < 2; i++) {
                int id  = tid + i * 256;          // 0..511
                int row = id >> 3, ch = id & 7;
                uint32_t off = SMEM_SWIZZLE_128B((uint32_t)(row * 128 + ch * 16));
                cp_async16(dbase + off, s + (size_t)row * CDIM + ch * 8);
            }
        }
    }
    // B splits: 128 rows x 8 chunks = 1024 cp16 each (4 per thread)
    {
        const __nv_bfloat16* srcs[2] = {bH + t * KT, bL + t * KT};
        #pragma unroll
        for (int b = 0; b < 2; b++) {
            const __nv_bfloat16* s = srcs[b];
            uint32_t dbase = sbase + 2 * A_BUF + b * B_BUF;
            #pragma unroll
            for (int i = 0; i < 4; i++) {
                int id  = tid + i * 256;          // 0..1023
                int row = id >> 3, ch = id & 7;
                uint32_t off = SMEM_SWIZZLE_128B((uint32_t)(row * 128 + ch * 16));
                cp_async16(dbase + off, s + (size_t)row * CDIM + ch * 8);
            }
        }
    }
}

__global__ __launch_bounds__(256, 2) void gemm_tc(
    const __nv_bfloat16* __restrict__ Ah, const __nv_bfloat16* __restrict__ Al,
    const __nv_bfloat16* __restrict__ Bh, const __nv_bfloat16* __restrict__ Bl,
    const float* __restrict__ bias, float* __restrict__ C, int Ntot)
{
    extern __shared__ __align__(128) char sb[];
    const uint32_t su = smem_to_u32(sb);

    const int tid    = threadIdx.x;
    const int wid    = tid >> 5;
    const int lane   = tid & 31;
    const int warp_m = wid & 1;      // 0..1 -> 32-row slab
    const int warp_n = wid >> 1;     // 0..3 -> 32-col slab
    const int brow   = blockIdx.y * BM;
    const int bcol   = blockIdx.x * BN;

    const __nv_bfloat16* aH = Ah + (size_t)brow * CDIM;
    const __nv_bfloat16* aL = Al + (size_t)brow * CDIM;
    const __nv_bfloat16* bH = Bh + (size_t)bcol * CDIM;
    const __nv_bfloat16* bL = Bl + (size_t)bcol * CDIM;

    // ldmatrix per-lane addressing: swizzle XOR (row&7) applied to the FINAL
    // 16B-chunk index (ch0 + 2*kk) inside the unrolled k loop. mi/g offsets
    // move by 16 rows -> row&7 invariant.
    const int aRow = warp_m * 32 + (lane & 15);
    const int aCh0 = lane >> 4;              // 0,1
    const uint32_t aXor    = (uint32_t)(aRow & 7);
    const uint32_t aRowOff = (uint32_t)aRow * 128;
    const int bRow = warp_n * 32 + (lane & 7) + ((lane >> 4) << 3);
    const int bCh0 = (lane >> 3) & 1;        // 0,1
    const uint32_t bXor    = (uint32_t)(bRow & 7);
    const uint32_t bRowOff = (uint32_t)bRow * 128;

    float acc[2][4][4];
    #pragma unroll
    for (int mi = 0; mi < 2; mi++)
        #pragma unroll
        for (int ni = 0; ni < 4; ni++)
            #pragma unroll
            for (int j = 0; j < 4; j++) acc[mi][ni][j] = 0.0f;

    stage_load(su, 0, tid, 0, aH, aL, bH, bL);
    cp_commit();

    for (int t = 0; t < NKT; t++) {
        if (t + 1 < NKT) {
            stage_load(su, (t + 1) & 1, tid, t + 1, aH, aL, bH, bL);
            cp_commit();
            cp_wait<1>();           // tile t landed, t+1 in flight
        } else {
            cp_wait<0>();
        }
        __syncthreads();

        const uint32_t sA  = su + (t & 1) * STAGE_BYTES;
        const uint32_t sAl = sA + A_BUF;
        const uint32_t sB  = sA + 2 * A_BUF;
        const uint32_t sBl = sB + B_BUF;

        #pragma unroll
        for (int kk = 0; kk < 4; kk++) {       // k16 steps within K-tile
            const uint32_t aOff =
                aRowOff + ((((uint32_t)(aCh0 + 2 * kk)) ^ aXor) << 4);
            const uint32_t bOff =
                bRowOff + ((((uint32_t)(bCh0 + 2 * kk)) ^ bXor) << 4);
            uint32_t ah[2][4], al[2][4], bh[2][4], bl[2][4];
            #pragma unroll
            for (int mi = 0; mi < 2; mi++) {
                ldmx4(ah[mi], sA  + aOff + mi * 2048);
                ldmx4(al[mi], sAl + aOff + mi * 2048);
            }
            #pragma unroll
            for (int g = 0; g < 2; g++) {      // n16 groups
                ldmx4(bh[g], sB  + bOff + g * 2048);
                ldmx4(bl[g], sBl + bOff + g * 2048);
            }
            #pragma unroll
            for (int mi = 0; mi < 2; mi++)
                #pragma unroll
                for (int ni = 0; ni < 4; ni++) {
                    const int g = ni >> 1, p = (ni & 1) * 2;
                    mma_bf16(acc[mi][ni], ah[mi], bh[g][p], bh[g][p + 1]);
                    mma_bf16(acc[mi][ni], ah[mi], bl[g][p], bl[g][p + 1]);
                    mma_bf16(acc[mi][ni], al[mi], bh[g][p], bh[g][p + 1]);
                }
        }
        __syncthreads();   // stage (t&1) free for reload at iteration t+1
    }

    // Epilogue: per mma frag, lane l -> rows l/4 & l/4+8, cols (l%4)*2 +{0,1}
    #pragma unroll
    for (int mi = 0; mi < 2; mi++) {
        const int r0 = brow + warp_m * 32 + mi * 16 + (lane >> 2);
        #pragma unroll
        for (int ni = 0; ni < 4; ni++) {
            const int col = bcol + warp_n * 32 + ni * 8 + (lane & 3) * 2;
            const float b0 = bias[col], b1 = bias[col + 1];
            float2 v0 = {acc[mi][ni][0] + b0, acc[mi][ni][1] + b1};
            float2 v1 = {acc[mi][ni][2] + b0, acc[mi][ni][3] + b1};
            *reinterpret_cast<float2*>(&C[(size_t)r0 * Ntot + col]) = v0;
            *reinterpret_cast<float2*>(&C[(size_t)(r0 + 8) * Ntot + col]) = v1;
        }
    }
}

// ---------------------------------------------------------------------------
// Windowed causal attention: one warp per (window, head). Reads fp32 qkv,
// writes bf16 hi/lo split directly (feeds GEMM3 A operand).
// ---------------------------------------------------------------------------
__global__ __launch_bounds__(256) void attn_window_kernel(
    const float* __restrict__ qkv,
    __nv_bfloat16* __restrict__ out_h, __nv_bfloat16* __restrict__ out_l)
{
    const int warp_global = blockIdx.x * 8 + (threadIdx.x >> 5);
    const int lane = threadIdx.x & 31;
    const int win  = warp_global >> 2;
    const int head = warp_global & 3;
    const float scale = 0.125f;

    const float* base = qkv + (size_t)win * 8 * QKVDIM + head * HDIM;

    float q[8][2], k[8][2], v[8][2];
    #pragma unroll
    for (int i = 0; i < 8; i++) {
        #pragma unroll
        for (int ld = 0; ld < 2; ld++) {
            int d = ld * 32 + lane;
            q[i][ld] = base[i * QKVDIM + d];
            k[i][ld] = base[i * QKVDIM + 256 + d];
            v[i][ld] = base[i * QKVDIM + 512 + d];
        }
    }

    float p[8][8];
    #pragma unroll
    for (int i = 0; i < 8; i++) {
        #pragma unroll
        for (int j = 0; j < 8; j++) {
            float s = q[i][0] * k[j][0] + q[i][1] * k[j][1];
            #pragma unroll
            for (int o = 16; o > 0; o >>= 1)
                s += __shfl_xor_sync(0xffffffffu, s, o);
            p[i][j] = s * scale;
        }
    }

    #pragma unroll
    for (int i = 0; i < 8; i++) {
        float mx = p[i][0];
        #pragma unroll
        for (int j = 1; j < 8; j++)
            if (j <= i) mx = fmaxf(mx, p[i][j]);
        float sum = 0.0f;
        #pragma unroll
        for (int j = 0; j < 8; j++) {
            if (j <= i) { float e = __expf(p[i][j] - mx); p[i][j] = e; sum += e; }
            else          p[i][j] = 0.0f;
        }
        float inv = 1.0f / sum;
        #pragma unroll
        for (int j = 0; j < 8; j++) p[i][j] *= inv;
    }

    const size_t obase = (size_t)win * 8 * CDIM + head * HDIM;
    #pragma unroll
    for (int i = 0; i < 8; i++) {
        #pragma unroll
        for (int ld = 0; ld < 2; ld++) {
            float a = 0.0f;
            #pragma unroll
            for (int j = 0; j < 8; j++)
                a = fmaf(p[i][j], v[j][ld], a);
            __nv_bfloat16 hh = __float2bfloat16(a);
            __nv_bfloat16 ll = __float2bfloat16(a - __bfloat162float(hh));
            out_h[obase + i * CDIM + ld * 32 + lane] = hh;
            out_l[obase + i * CDIM + ld * 32 + lane] = ll;
        }
    }
}

// ---------------------------------------------------------------------------
// Launch
// ---------------------------------------------------------------------------
extern "C" void kernel_launch(void* const* d_in, const int* in_sizes, int n_in,
                              void* d_out, int out_size)
{
    const float* x      = (const float*)d_in[0];
    const float* w_qkv  = (const float*)d_in[1];
    const float* b_qkv  = (const float*)d_in[2];
    const float* w_proj = (const float*)d_in[3];
    const float* b_proj = (const float*)d_in[4];
    float* out = (float*)d_out;

    float* qkv_buf;
    __nv_bfloat16 *xh, *xl, *ath, *atl, *wqh, *wql, *wph, *wpl;
    cudaGetSymbolAddress((void**)&qkv_buf, g_qkv);
    cudaGetSymbolAddress((void**)&xh,  g_xh);
    cudaGetSymbolAddress((void**)&xl,  g_xl);
    cudaGetSymbolAddress((void**)&ath, g_ath);
    cudaGetSymbolAddress((void**)&atl, g_atl);
    cudaGetSymbolAddress((void**)&wqh, g_wqh);
    cudaGetSymbolAddress((void**)&wql, g_wql);
    cudaGetSymbolAddress((void**)&wph, g_wph);
    cudaGetSymbolAddress((void**)&wpl, g_wpl);

    cudaFuncSetAttribute(gemm_tc, cudaFuncAttributeMaxDynamicSharedMemorySize,
                         GEMM_SMEM);

    // Split-convert inputs and weights to bf16 hi/lo
    convert_split<<<(TOKENS * CDIM / 4) / 256, 256>>>(x, xh, xl, TOKENS * CDIM / 4);
    convert_split<<<(QKVDIM * CDIM / 4) / 256, 256>>>(w_qkv, wqh, wql, QKVDIM * CDIM / 4);
    convert_split<<<(CDIM * CDIM / 4) / 256, 256>>>(w_proj, wph, wpl, CDIM * CDIM / 4);

    // K1: qkv = x @ w_qkv^T + b_qkv   (M=131072, N=768, K=256)
    {
        dim3 grid(QKVDIM / BN, TOKENS / BM);
        gemm_tc<<<grid, 256, GEMM_SMEM>>>(xh, xl, wqh, wql, b_qkv, qkv_buf, QKVDIM);
    }

    // K2: windowed causal attention -> bf16 hi/lo
    attn_window_kernel<<<(NWIN * NHEAD) / 8, 256>>>(qkv_buf, ath, atl);

    // K3: out = att @ w_proj^T + b_proj  (M=131072, N=256, K=256)
    {
        dim3 grid(CDIM / BN, TOKENS / BM);
        gemm_tc<<<grid, 256, GEMM_SMEM>>>(ath, atl, wph, wpl, b_proj, out, CDIM);
    }
}

// round 11
// speedup vs baseline: 4.2421x; 1.0658x over previous
#include <cuda_runtime.h>
#include <cuda_bf16.h>
#include <cstdint>

// ---------------------------------------------------------------------------
// Problem constants
// ---------------------------------------------------------------------------
#define TOKENS   131072      // 32 * 4096
#define CDIM     256
#define QKVDIM   768
#define NWIN     16384
#define NHEAD    4
#define HDIM     64

// ---------------------------------------------------------------------------
// Scratch (device globals — no runtime allocation allowed)
// ---------------------------------------------------------------------------
__device__ float g_qkv[(size_t)TOKENS * QKVDIM];  // fp32 qkv
__device__ __align__(16) __nv_bfloat16 g_xh [(size_t)TOKENS * CDIM];
__device__ __align__(16) __nv_bfloat16 g_xl [(size_t)TOKENS * CDIM];
__device__ __align__(16) __nv_bfloat16 g_ath[(size_t)TOKENS * CDIM];
__device__ __align__(16) __nv_bfloat16 g_atl[(size_t)TOKENS * CDIM];
__device__ __align__(16) __nv_bfloat16 g_wqh[(size_t)QKVDIM * CDIM];
__device__ __align__(16) __nv_bfloat16 g_wql[(size_t)QKVDIM * CDIM];
__device__ __align__(16) __nv_bfloat16 g_wph[(size_t)CDIM * CDIM];
__device__ __align__(16) __nv_bfloat16 g_wpl[(size_t)CDIM * CDIM];

// ---------------------------------------------------------------------------
// Low-level helpers (sm_80-era ISA only: ldmatrix / mma.sync / cp.async)
// ---------------------------------------------------------------------------
__device__ __forceinline__ uint32_t smem_to_u32(const void* p) {
    uint32_t a;
    asm("{ .reg .u64 t; cvta.to.shared.u64 t, %1; cvt.u32.u64 %0, t; }"
        : "=r"(a) : "l"(p));
    return a;
}

__device__ __forceinline__ void cp_async16(uint32_t dst, const void* src) {
    asm volatile("cp.async.cg.shared.global [%0], [%1], 16;"
                 :: "r"(dst), "l"(src));
}
__device__ __forceinline__ void cp_commit() {
    asm volatile("cp.async.commit_group;");
}
template <int N>
__device__ __forceinline__ void cp_wait() {
    asm volatile("cp.async.wait_group %0;" :: "n"(N));
}

__device__ __forceinline__ void ldmx4(uint32_t* r, uint32_t addr) {
    asm volatile("ldmatrix.sync.aligned.m8n8.x4.shared.b16 {%0,%1,%2,%3}, [%4];"
                 : "=r"(r[0]), "=r"(r[1]), "=r"(r[2]), "=r"(r[3]) : "r"(addr));
}

__device__ __forceinline__ void mma_bf16(float* d, const uint32_t* a,
                                         uint32_t b0, uint32_t b1) {
    asm volatile(
        "mma.sync.aligned.m16n8k16.row.col.f32.bf16.bf16.f32 "
        "{%0,%1,%2,%3}, {%4,%5,%6,%7}, {%8,%9}, {%0,%1,%2,%3};"
        : "+f"(d[0]), "+f"(d[1]), "+f"(d[2]), "+f"(d[3])
        : "r"(a[0]), "r"(a[1]), "r"(a[2]), "r"(a[3]), "r"(b0), "r"(b1));
}

#define SMEM_SWIZZLE_128B(off) ((off) ^ (((off) >> 3) & 0x70))

// ---------------------------------------------------------------------------
// Split-convert: fp32 -> (hi, lo) bf16 pair (error-free 2-term split)
// ---------------------------------------------------------------------------
__global__ __launch_bounds__(256) void convert_split(
    const float* __restrict__ src,
    __nv_bfloat16* __restrict__ hi, __nv_bfloat16* __restrict__ lo, int n4)
{
    int i = blockIdx.x * blockDim.x + threadIdx.x;
    if (i >= n4) return;
    float4 v = reinterpret_cast<const float4*>(src)[i];
    float f[4] = {v.x, v.y, v.z, v.w};
    __nv_bfloat16 h[4], l[4];
    #pragma unroll
    for (int j = 0; j < 4; j++) {
        h[j] = __float2bfloat16(f[j]);
        l[j] = __float2bfloat16(f[j] - __bfloat162float(h[j]));
    }
    __nv_bfloat162* ph = reinterpret_cast<__nv_bfloat162*>(hi + (size_t)i * 4);
    __nv_bfloat162* pl = reinterpret_cast<__nv_bfloat162*>(lo + (size_t)i * 4);
    ph[0] = __halves2bfloat162(h[0], h[1]);
    ph[1] = __halves2bfloat162(h[2], h[3]);
    pl[0] = __halves2bfloat162(l[0], l[1]);
    pl[1] = __halves2bfloat162(l[2], l[3]);
}

// ---------------------------------------------------------------------------
// Persistent HMMA GEMM: C[M,Ntot] = (Ah+Al)[M,256] @ (Bh+Bl)[Ntot,256]^T + bias
// CTA 64x128, 8 warps (2m x 4n), warp tile 32x32, mma.m16n8k16 bf16.
// K-tiles of 64 (128B SW128-swizzled rows), cp.async double-buffered with the
// pipeline running CONTINUOUSLY across tile boundaries (persistent CTAs:
// grid = 2/SM, each CTA strides the tile list; next tile's k0 load is issued
// during the current tile's last k-step so epilogue/prologue overlap compute).
// 3-term split: Ah*Bh + Ah*Bl + Al*Bh accumulated in fp32.
// 2 CTAs/SM: 96KB smem, <=128 regs.
// ---------------------------------------------------------------------------
#define BM 64
#define BN 128
#define KT 64
#define NKT 4                        // 256 / 64
#define A_BUF 8192                   // 64 rows * 128 B
#define B_BUF 16384                  // 128 rows * 128 B
#define STAGE_BYTES (2 * A_BUF + 2 * B_BUF)   // Ah, Al, Bh, Bl = 49152
#define GEMM_SMEM   (2 * STAGE_BYTES)         // 98304
#define GEMM_GRID   304              // 2 CTAs/SM * 152 SMs (GB300)

static __device__ __forceinline__ void stage_load(
    uint32_t su, int stage, int tid,
    const __nv_bfloat16* __restrict__ aH, const __nv_bfloat16* __restrict__ aL,
    const __nv_bfloat16* __restrict__ bH, const __nv_bfloat16* __restrict__ bL)
{
    const uint32_t sbase = su + stage * STAGE_BYTES;
    // A splits: 64 rows x 8 chunks = 512 cp16 each (2 per thread)
    {
        const __nv_bfloat16* srcs[2] = {aH, aL};
        #pragma unroll
        for (int b = 0; b < 2; b++) {
            const __nv_bfloat16* s = srcs[b];
            uint32_t dbase = sbase + b * A_BUF;
            #pragma unroll
            for (int i = 0; i < 2; i++) {
                int id  = tid + i * 256;          // 0..511
                int row = id >> 3, ch = id & 7;
                uint32_t off = SMEM_SWIZZLE_128B((uint32_t)(row * 128 + ch * 16));
                cp_async16(dbase + off, s + (size_t)row * CDIM + ch * 8);
            }
        }
    }
    // B splits: 128 rows x 8 chunks = 1024 cp16 each (4 per thread)
    {
        const __nv_bfloat16* srcs[2] = {bH, bL};
        #pragma unroll
        for (int b = 0; b < 2; b++) {
            const __nv_bfloat16* s = srcs[b];
            uint32_t dbase = sbase + 2 * A_BUF + b * B_BUF;
            #pragma unroll
            for (int i = 0; i < 4; i++) {
                int id  = tid + i * 256;          // 0..1023
                int row = id >> 3, ch = id & 7;
                uint32_t off = SMEM_SWIZZLE_128B((uint32_t)(row * 128 + ch * 16));
                cp_async16(dbase + off, s + (size_t)row * CDIM + ch * 8);
            }
        }
    }
}

__global__ __launch_bounds__(256, 2) void gemm_tc(
    const __nv_bfloat16* __restrict__ Ah, const __nv_bfloat16* __restrict__ Al,
    const __nv_bfloat16* __restrict__ Bh, const __nv_bfloat16* __restrict__ Bl,
    const float* __restrict__ bias, float* __restrict__ C,
    int Ntot, int ntiles, int gx)
{
    extern __shared__ __align__(128) char sb[];
    const uint32_t su = smem_to_u32(sb);

    const int tid    = threadIdx.x;
    const int wid    = tid >> 5;
    const int lane   = tid & 31;
    const int warp_m = wid & 1;      // 0..1 -> 32-row slab
    const int warp_n = wid >> 1;     // 0..3 -> 32-col slab
    const int nct    = (int)gridDim.x;

    // ldmatrix per-lane addressing: swizzle XOR (row&7) applied to the FINAL
    // 16B-chunk index (ch0 + 2*kk) inside the unrolled k loop. mi/g offsets
    // move by 16 rows -> row&7 invariant.
    const int aRow = warp_m * 32 + (lane & 15);
    const int aCh0 = lane >> 4;              // 0,1
    const uint32_t aXor    = (uint32_t)(aRow & 7);
    const uint32_t aRowOff = (uint32_t)aRow * 128;
    const int bRow = warp_n * 32 + (lane & 7) + ((lane >> 4) << 3);
    const int bCh0 = (lane >> 3) & 1;        // 0,1
    const uint32_t bXor    = (uint32_t)(bRow & 7);
    const uint32_t bRowOff = (uint32_t)bRow * 128;

    int tile = blockIdx.x;
    if (tile >= ntiles) return;

    // Preload k-tile 0 of the first tile into stage 0.
    {
        const size_t aOff = (size_t)(tile / gx) * BM * CDIM;
        const size_t bOff = (size_t)(tile % gx) * BN * CDIM;
        stage_load(su, 0, tid, Ah + aOff, Al + aOff, Bh + bOff, Bl + bOff);
        cp_commit();
    }
    int parity = 0;

    for (; tile < ntiles; tile += nct) {
        const int brow = (tile / gx) * BM;
        const int bcol = (tile % gx) * BN;
        const __nv_bfloat16* aH = Ah + (size_t)brow * CDIM;
        const __nv_bfloat16* aL = Al + (size_t)brow * CDIM;
        const __nv_bfloat16* bH = Bh + (size_t)bcol * CDIM;
        const __nv_bfloat16* bL = Bl + (size_t)bcol * CDIM;

        const int nextTile = tile + nct;
        const bool hasNext = nextTile < ntiles;
        const size_t naOff = hasNext ? (size_t)(nextTile / gx) * BM * CDIM : 0;
        const size_t nbOff = hasNext ? (size_t)(nextTile % gx) * BN * CDIM : 0;

        float acc[2][4][4];
        #pragma unroll
        for (int mi = 0; mi < 2; mi++)
            #pragma unroll
            for (int ni = 0; ni < 4; ni++)
                #pragma unroll
                for (int j = 0; j < 4; j++) acc[mi][ni][j] = 0.0f;

        #pragma unroll
        for (int t = 0; t < NKT; t++) {
            // Issue the NEXT chunk (next k-tile, or next tile's k0) into the
            // other stage, keeping the cp.async stream continuous.
            if (t + 1 < NKT) {
                stage_load(su, parity ^ 1, tid,
                           aH + (t + 1) * KT, aL + (t + 1) * KT,
                           bH + (t + 1) * KT, bL + (t + 1) * KT);
                cp_commit();
                cp_wait<1>();
            } else if (hasNext) {
                stage_load(su, parity ^ 1, tid,
                           Ah + naOff, Al + naOff, Bh + nbOff, Bl + nbOff);
                cp_commit();
                cp_wait<1>();
            } else {
                cp_wait<0>();
            }
            __syncthreads();

            const uint32_t sA  = su + parity * STAGE_BYTES;
            const uint32_t sAl = sA + A_BUF;
            const uint32_t sB  = sA + 2 * A_BUF;
            const uint32_t sBl = sB + B_BUF;

            #pragma unroll
            for (int kk = 0; kk < 4; kk++) {       // k16 steps within K-tile
                const uint32_t aOff =
                    aRowOff + ((((uint32_t)(aCh0 + 2 * kk)) ^ aXor) << 4);
                const uint32_t bOff =
                    bRowOff + ((((uint32_t)(bCh0 + 2 * kk)) ^ bXor) << 4);
                uint32_t ah[2][4], al[2][4], bh[2][4], bl[2][4];
                #pragma unroll
                for (int mi = 0; mi < 2; mi++) {
                    ldmx4(ah[mi], sA  + aOff + mi * 2048);
                    ldmx4(al[mi], sAl + aOff + mi * 2048);
                }
                #pragma unroll
                for (int g = 0; g < 2; g++) {      // n16 groups
                    ldmx4(bh[g], sB  + bOff + g * 2048);
                    ldmx4(bl[g], sBl + bOff + g * 2048);
                }
                #pragma unroll
                for (int mi = 0; mi < 2; mi++)
                    #pragma unroll
                    for (int ni = 0; ni < 4; ni++) {
                        const int g = ni >> 1, p = (ni & 1) * 2;
                        mma_bf16(acc[mi][ni], ah[mi], bh[g][p], bh[g][p + 1]);
                        mma_bf16(acc[mi][ni], ah[mi], bl[g][p], bl[g][p + 1]);
                        mma_bf16(acc[mi][ni], al[mi], bh[g][p], bh[g][p + 1]);
                    }
            }
            __syncthreads();   // stage `parity` free for the next issue
            parity ^= 1;
        }

        // Epilogue (overlaps next tile's k0 cp.async already in flight).
        // Per mma frag, lane l -> rows l/4 & l/4+8, cols (l%4)*2 + {0,1}.
        #pragma unroll
        for (int mi = 0; mi < 2; mi++) {
            const int r0 = brow + warp_m * 32 + mi * 16 + (lane >> 2);
            #pragma unroll
            for (int ni = 0; ni < 4; ni++) {
                const int col = bcol + warp_n * 32 + ni * 8 + (lane & 3) * 2;
                const float b0 = bias[col], b1 = bias[col + 1];
                float2 v0 = {acc[mi][ni][0] + b0, acc[mi][ni][1] + b1};
                float2 v1 = {acc[mi][ni][2] + b0, acc[mi][ni][3] + b1};
                *reinterpret_cast<float2*>(&C[(size_t)r0 * Ntot + col]) = v0;
                *reinterpret_cast<float2*>(&C[(size_t)(r0 + 8) * Ntot + col]) = v1;
            }
        }
    }
}

// ---------------------------------------------------------------------------
// Windowed causal attention: one warp per (window, head). Reads fp32 qkv,
// writes bf16 hi/lo split directly (feeds GEMM3 A operand).
// ---------------------------------------------------------------------------
__global__ __launch_bounds__(256) void attn_window_kernel(
    const float* __restrict__ qkv,
    __nv_bfloat16* __restrict__ out_h, __nv_bfloat16* __restrict__ out_l)
{
    const int warp_global = blockIdx.x * 8 + (threadIdx.x >> 5);
    const int lane = threadIdx.x & 31;
    const int win  = warp_global >> 2;
    const int head = warp_global & 3;
    const float scale = 0.125f;

    const float* base = qkv + (size_t)win * 8 * QKVDIM + head * HDIM;

    float q[8][2], k[8][2], v[8][2];
    #pragma unroll
    for (int i = 0; i < 8; i++) {
        #pragma unroll
        for (int ld = 0; ld < 2; ld++) {
            int d = ld * 32 + lane;
            q[i][ld] = base[i * QKVDIM + d];
            k[i][ld] = base[i * QKVDIM + 256 + d];
            v[i][ld] = base[i * QKVDIM + 512 + d];
        }
    }

    float p[8][8];
    #pragma unroll
    for (int i = 0; i < 8; i++) {
        #pragma unroll
        for (int j = 0; j < 8; j++) {
            float s = q[i][0] * k[j][0] + q[i][1] * k[j][1];
            #pragma unroll
            for (int o = 16; o > 0; o >>= 1)
                s += __shfl_xor_sync(0xffffffffu, s, o);
            p[i][j] = s * scale;
        }
    }

    #pragma unroll
    for (int i = 0; i < 8; i++) {
        float mx = p[i][0];
        #pragma unroll
        for (int j = 1; j < 8; j++)
            if (j <= i) mx = fmaxf(mx, p[i][j]);
        float sum = 0.0f;
        #pragma unroll
        for (int j = 0; j < 8; j++) {
            if (j <= i) { float e = __expf(p[i][j] - mx); p[i][j] = e; sum += e; }
            else          p[i][j] = 0.0f;
        }
        float inv = 1.0f / sum;
        #pragma unroll
        for (int j = 0; j < 8; j++) p[i][j] *= inv;
    }

    const size_t obase = (size_t)win * 8 * CDIM + head * HDIM;
    #pragma unroll
    for (int i = 0; i < 8; i++) {
        #pragma unroll
        for (int ld = 0; ld < 2; ld++) {
            float a = 0.0f;
            #pragma unroll
            for (int j = 0; j < 8; j++)
                a = fmaf(p[i][j], v[j][ld], a);
            __nv_bfloat16 hh = __float2bfloat16(a);
            __nv_bfloat16 ll = __float2bfloat16(a - __bfloat162float(hh));
            out_h[obase + i * CDIM + ld * 32 + lane] = hh;
            out_l[obase + i * CDIM + ld * 32 + lane] = ll;
        }
    }
}

// ---------------------------------------------------------------------------
// Launch
// ---------------------------------------------------------------------------
extern "C" void kernel_launch(void* const* d_in, const int* in_sizes, int n_in,
                              void* d_out, int out_size)
{
    const float* x      = (const float*)d_in[0];
    const float* w_qkv  = (const float*)d_in[1];
    const float* b_qkv  = (const float*)d_in[2];
    const float* w_proj = (const float*)d_in[3];
    const float* b_proj = (const float*)d_in[4];
    float* out = (float*)d_out;

    float* qkv_buf;
    __nv_bfloat16 *xh, *xl, *ath, *atl, *wqh, *wql, *wph, *wpl;
    cudaGetSymbolAddress((void**)&qkv_buf, g_qkv);
    cudaGetSymbolAddress((void**)&xh,  g_xh);
    cudaGetSymbolAddress((void**)&xl,  g_xl);
    cudaGetSymbolAddress((void**)&ath, g_ath);
    cudaGetSymbolAddress((void**)&atl, g_atl);
    cudaGetSymbolAddress((void**)&wqh, g_wqh);
    cudaGetSymbolAddress((void**)&wql, g_wql);
    cudaGetSymbolAddress((void**)&wph, g_wph);
    cudaGetSymbolAddress((void**)&wpl, g_wpl);

    cudaFuncSetAttribute(gemm_tc, cudaFuncAttributeMaxDynamicSharedMemorySize,
                         GEMM_SMEM);

    // Split-convert inputs and weights to bf16 hi/lo
    convert_split<<<(TOKENS * CDIM / 4) / 256, 256>>>(x, xh, xl, TOKENS * CDIM / 4);
    convert_split<<<(QKVDIM * CDIM / 4) / 256, 256>>>(w_qkv, wqh, wql, QKVDIM * CDIM / 4);
    convert_split<<<(CDIM * CDIM / 4) / 256, 256>>>(w_proj, wph, wpl, CDIM * CDIM / 4);

    // K1: qkv = x @ w_qkv^T + b_qkv   (M=131072, N=768, K=256)
    {
        const int gx = QKVDIM / BN;              // 6
        const int ntiles = gx * (TOKENS / BM);   // 12288
        gemm_tc<<<GEMM_GRID, 256, GEMM_SMEM>>>(xh, xl, wqh, wql, b_qkv,
                                               qkv_buf, QKVDIM, ntiles, gx);
    }

    // K2: windowed causal attention -> bf16 hi/lo
    attn_window_kernel<<<(NWIN * NHEAD) / 8, 256>>>(qkv_buf, ath, atl);

    // K3: out = att @ w_proj^T + b_proj  (M=131072, N=256, K=256)
    {
        const int gx = CDIM / BN;                // 2
        const int ntiles = gx * (TOKENS / BM);   // 4096
        gemm_tc<<<GEMM_GRID, 256, GEMM_SMEM>>>(ath, atl, wph, wpl, b_proj,
                                               out, CDIM, ntiles, gx);
    }
}

// round 12
// speedup vs baseline: 5.2797x; 1.2446x over previous
#include <cuda_runtime.h>
#include <cuda_fp16.h>
#include <cstdint>

// ---------------------------------------------------------------------------
// Problem constants
// ---------------------------------------------------------------------------
#define TOKENS   131072      // 32 * 4096
#define CDIM     256
#define QKVDIM   768
#define NWIN     16384
#define NHEAD    4
#define HDIM     64

// ---------------------------------------------------------------------------
// Scratch (device globals — no runtime allocation allowed)
// ---------------------------------------------------------------------------
__device__ float g_qkv[(size_t)TOKENS * QKVDIM];  // fp32 qkv
__device__ __align__(16) __half g_xh [(size_t)TOKENS * CDIM];   // fp16(x)
__device__ __align__(16) __half g_ath[(size_t)TOKENS * CDIM];   // fp16(att)
__device__ __align__(16) __half g_wqh[(size_t)QKVDIM * CDIM];
__device__ __align__(16) __half g_wql[(size_t)QKVDIM * CDIM];
__device__ __align__(16) __half g_wph[(size_t)CDIM * CDIM];
__device__ __align__(16) __half g_wpl[(size_t)CDIM * CDIM];

// ---------------------------------------------------------------------------
// Low-level helpers (sm_80-era ISA only: ldmatrix / mma.sync / cp.async)
// ---------------------------------------------------------------------------
__device__ __forceinline__ uint32_t smem_to_u32(const void* p) {
    uint32_t a;
    asm("{ .reg .u64 t; cvta.to.shared.u64 t, %1; cvt.u32.u64 %0, t; }"
        : "=r"(a) : "l"(p));
    return a;
}

__device__ __forceinline__ void cp_async16(uint32_t dst, const void* src) {
    asm volatile("cp.async.cg.shared.global [%0], [%1], 16;"
                 :: "r"(dst), "l"(src));
}
__device__ __forceinline__ void cp_commit() {
    asm volatile("cp.async.commit_group;");
}
template <int N>
__device__ __forceinline__ void cp_wait() {
    asm volatile("cp.async.wait_group %0;" :: "n"(N));
}

__device__ __forceinline__ void ldmx4(uint32_t* r, uint32_t addr) {
    asm volatile("ldmatrix.sync.aligned.m8n8.x4.shared.b16 {%0,%1,%2,%3}, [%4];"
                 : "=r"(r[0]), "=r"(r[1]), "=r"(r[2]), "=r"(r[3]) : "r"(addr));
}

__device__ __forceinline__ void mma_f16(float* d, const uint32_t* a,
                                        uint32_t b0, uint32_t b1) {
    asm volatile(
        "mma.sync.aligned.m16n8k16.row.col.f32.f16.f16.f32 "
        "{%0,%1,%2,%3}, {%4,%5,%6,%7}, {%8,%9}, {%0,%1,%2,%3};"
        : "+f"(d[0]), "+f"(d[1]), "+f"(d[2]), "+f"(d[3])
        : "r"(a[0]), "r"(a[1]), "r"(a[2]), "r"(a[3]), "r"(b0), "r"(b1));
}

#define SMEM_SWIZZLE_128B(off) ((off) ^ (((off) >> 3) & 0x70))

// ---------------------------------------------------------------------------
// Converts: fp32 -> fp16 (A side), fp32 -> (hi, lo) fp16 pair (B side)
// ---------------------------------------------------------------------------
__global__ __launch_bounds__(256) void convert_h(
    const float* __restrict__ src, __half* __restrict__ dst, int n4)
{
    int i = blockIdx.x * blockDim.x + threadIdx.x;
    if (i >= n4) return;
    float4 v = reinterpret_cast<const float4*>(src)[i];
    __half2* p = reinterpret_cast<__half2*>(dst + (size_t)i * 4);
    p[0] = __floats2half2_rn(v.x, v.y);
    p[1] = __floats2half2_rn(v.z, v.w);
}

__global__ __launch_bounds__(256) void convert_split(
    const float* __restrict__ src,
    __half* __restrict__ hi, __half* __restrict__ lo, int n4)
{
    int i = blockIdx.x * blockDim.x + threadIdx.x;
    if (i >= n4) return;
    float4 v = reinterpret_cast<const float4*>(src)[i];
    float f[4] = {v.x, v.y, v.z, v.w};
    __half h[4], l[4];
    #pragma unroll
    for (int j = 0; j < 4; j++) {
        h[j] = __float2half_rn(f[j]);
        l[j] = __float2half_rn(f[j] - __half2float(h[j]));
    }
    __half2* ph = reinterpret_cast<__half2*>(hi + (size_t)i * 4);
    __half2* pl = reinterpret_cast<__half2*>(lo + (size_t)i * 4);
    ph[0] = __halves2half2(h[0], h[1]);
    ph[1] = __halves2half2(h[2], h[3]);
    pl[0] = __halves2half2(l[0], l[1]);
    pl[1] = __halves2half2(l[2], l[3]);
}

// ---------------------------------------------------------------------------
// Persistent HMMA GEMM: C[M,Ntot] = A[M,256] @ (Bh+Bl)[Ntot,256]^T + bias
// A single fp16, B 2-term fp16 split -> 2 MMAs per (k16, 16x8) tile.
// CTA 64x128, 8 warps (2m x 4n), warp tile 32x32, mma.m16n8k16 f16.
// K-tiles of 64 (128B SW128-swizzled rows), cp.async double-buffered with the
// pipeline continuous across tile boundaries (persistent CTAs).
// ---------------------------------------------------------------------------
#define BM 64
#define BN 128
#define KT 64
#define NKT 4                        // 256 / 64
#define A_BUF 8192                   // 64 rows * 128 B
#define B_BUF 16384                  // 128 rows * 128 B
#define STAGE_BYTES (A_BUF + 2 * B_BUF)       // A, Bh, Bl = 40960
#define GEMM_SMEM   (2 * STAGE_BYTES)         // 81920
#define GEMM_GRID   304              // 2 CTAs/SM * 152 SMs (GB300)

static __device__ __forceinline__ void stage_load(
    uint32_t su, int stage, int tid,
    const __half* __restrict__ aH,
    const __half* __restrict__ bH, const __half* __restrict__ bL)
{
    const uint32_t sbase = su + stage * STAGE_BYTES;
    // A: 64 rows x 8 chunks = 512 cp16 (2 per thread)
    #pragma unroll
    for (int i = 0; i < 2; i++) {
        int id  = tid + i * 256;          // 0..511
        int row = id >> 3, ch = id & 7;
        uint32_t off = SMEM_SWIZZLE_128B((uint32_t)(row * 128 + ch * 16));
        cp_async16(sbase + off, aH + (size_t)row * CDIM + ch * 8);
    }
    // B splits: 128 rows x 8 chunks = 1024 cp16 each (4 per thread)
    {
        const __half* srcs[2] = {bH, bL};
        #pragma unroll
        for (int b = 0; b < 2; b++) {
            const __half* s = srcs[b];
            uint32_t dbase = sbase + A_BUF + b * B_BUF;
            #pragma unroll
            for (int i = 0; i < 4; i++) {
                int id  = tid + i * 256;          // 0..1023
                int row = id >> 3, ch = id & 7;
                uint32_t off = SMEM_SWIZZLE_128B((uint32_t)(row * 128 + ch * 16));
                cp_async16(dbase + off, s + (size_t)row * CDIM + ch * 8);
            }
        }
    }
}

__global__ __launch_bounds__(256, 2) void gemm_tc(
    const __half* __restrict__ Ah,
    const __half* __restrict__ Bh, const __half* __restrict__ Bl,
    const float* __restrict__ bias, float* __restrict__ C,
    int Ntot, int ntiles, int gx)
{
    extern __shared__ __align__(128) char sb[];
    const uint32_t su = smem_to_u32(sb);

    const int tid    = threadIdx.x;
    const int wid    = tid >> 5;
    const int lane   = tid & 31;
    const int warp_m = wid & 1;      // 0..1 -> 32-row slab
    const int warp_n = wid >> 1;     // 0..3 -> 32-col slab
    const int nct    = (int)gridDim.x;

    // ldmatrix per-lane addressing: swizzle XOR (row&7) applied to the FINAL
    // 16B-chunk index (ch0 + 2*kk) inside the unrolled k loop.
    const int aRow = warp_m * 32 + (lane & 15);
    const int aCh0 = lane >> 4;              // 0,1
    const uint32_t aXor    = (uint32_t)(aRow & 7);
    const uint32_t aRowOff = (uint32_t)aRow * 128;
    const int bRow = warp_n * 32 + (lane & 7) + ((lane >> 4) << 3);
    const int bCh0 = (lane >> 3) & 1;        // 0,1
    const uint32_t bXor    = (uint32_t)(bRow & 7);
    const uint32_t bRowOff = (uint32_t)bRow * 128;

    int tile = blockIdx.x;
    if (tile >= ntiles) return;

    // Preload k-tile 0 of the first tile into stage 0.
    {
        const size_t aOff = (size_t)(tile / gx) * BM * CDIM;
        const size_t bOff = (size_t)(tile % gx) * BN * CDIM;
        stage_load(su, 0, tid, Ah + aOff, Bh + bOff, Bl + bOff);
        cp_commit();
    }
    int parity = 0;

    for (; tile < ntiles; tile += nct) {
        const int brow = (tile / gx) * BM;
        const int bcol = (tile % gx) * BN;
        const __half* aH = Ah + (size_t)brow * CDIM;
        const __half* bH = Bh + (size_t)bcol * CDIM;
        const __half* bL = Bl + (size_t)bcol * CDIM;

        const int nextTile = tile + nct;
        const bool hasNext = nextTile < ntiles;
        const size_t naOff = hasNext ? (size_t)(nextTile / gx) * BM * CDIM : 0;
        const size_t nbOff = hasNext ? (size_t)(nextTile % gx) * BN * CDIM : 0;

        float acc[2][4][4];
        #pragma unroll
        for (int mi = 0; mi < 2; mi++)
            #pragma unroll
            for (int ni = 0; ni < 4; ni++)
                #pragma unroll
                for (int j = 0; j < 4; j++) acc[mi][ni][j] = 0.0f;

        #pragma unroll
        for (int t = 0; t < NKT; t++) {
            // Issue the NEXT chunk (next k-tile, or next tile's k0) into the
            // other stage, keeping the cp.async stream continuous.
            if (t + 1 < NKT) {
                stage_load(su, parity ^ 1, tid,
                           aH + (t + 1) * KT, bH + (t + 1) * KT,
                           bL + (t + 1) * KT);
                cp_commit();
                cp_wait<1>();
            } else if (hasNext) {
                stage_load(su, parity ^ 1, tid,
                           Ah + naOff, Bh + nbOff, Bl + nbOff);
                cp_commit();
                cp_wait<1>();
            } else {
                cp_wait<0>();
            }
            __syncthreads();

            const uint32_t sA  = su + parity * STAGE_BYTES;
            const uint32_t sB  = sA + A_BUF;
            const uint32_t sBl = sB + B_BUF;

            #pragma unroll
            for (int kk = 0; kk < 4; kk++) {       // k16 steps within K-tile
                const uint32_t aOff =
                    aRowOff + ((((uint32_t)(aCh0 + 2 * kk)) ^ aXor) << 4);
                const uint32_t bOff =
                    bRowOff + ((((uint32_t)(bCh0 + 2 * kk)) ^ bXor) << 4);
                uint32_t ah[2][4], bh[2][4], bl[2][4];
                #pragma unroll
                for (int mi = 0; mi < 2; mi++)
                    ldmx4(ah[mi], sA  + aOff + mi * 2048);
                #pragma unroll
                for (int g = 0; g < 2; g++) {      // n16 groups
                    ldmx4(bh[g], sB  + bOff + g * 2048);
                    ldmx4(bl[g], sBl + bOff + g * 2048);
                }
                #pragma unroll
                for (int mi = 0; mi < 2; mi++)
                    #pragma unroll
                    for (int ni = 0; ni < 4; ni++) {
                        const int g = ni >> 1, p = (ni & 1) * 2;
                        mma_f16(acc[mi][ni], ah[mi], bh[g][p], bh[g][p + 1]);
                        mma_f16(acc[mi][ni], ah[mi], bl[g][p], bl[g][p + 1]);
                    }
            }
            __syncthreads();   // stage `parity` free for the next issue
            parity ^= 1;
        }

        // Epilogue (overlaps next tile's k0 cp.async already in flight).
        #pragma unroll
        for (int mi = 0; mi < 2; mi++) {
            const int r0 = brow + warp_m * 32 + mi * 16 + (lane >> 2);
            #pragma unroll
            for (int ni = 0; ni < 4; ni++) {
                const int col = bcol + warp_n * 32 + ni * 8 + (lane & 3) * 2;
                const float b0 = bias[col], b1 = bias[col + 1];
                float2 v0 = {acc[mi][ni][0] + b0, acc[mi][ni][1] + b1};
                float2 v1 = {acc[mi][ni][2] + b0, acc[mi][ni][3] + b1};
                *reinterpret_cast<float2*>(&C[(size_t)r0 * Ntot + col]) = v0;
                *reinterpret_cast<float2*>(&C[(size_t)(r0 + 8) * Ntot + col]) = v1;
            }
        }
    }
}

// ---------------------------------------------------------------------------
// Windowed causal attention: one warp per (window, head). Reads fp32 qkv,
// writes fp16 directly (feeds GEMM3 A operand).
// ---------------------------------------------------------------------------
__global__ __launch_bounds__(256) void attn_window_kernel(
    const float* __restrict__ qkv, __half* __restrict__ out_h)
{
    const int warp_global = blockIdx.x * 8 + (threadIdx.x >> 5);
    const int lane = threadIdx.x & 31;
    const int win  = warp_global >> 2;
    const int head = warp_global & 3;
    const float scale = 0.125f;

    const float* base = qkv + (size_t)win * 8 * QKVDIM + head * HDIM;

    float q[8][2], k[8][2], v[8][2];
    #pragma unroll
    for (int i = 0; i < 8; i++) {
        #pragma unroll
        for (int ld = 0; ld < 2; ld++) {
            int d = ld * 32 + lane;
            q[i][ld] = base[i * QKVDIM + d];
            k[i][ld] = base[i * QKVDIM + 256 + d];
            v[i][ld] = base[i * QKVDIM + 512 + d];
        }
    }

    float p[8][8];
    #pragma unroll
    for (int i = 0; i < 8; i++) {
        #pragma unroll
        for (int j = 0; j < 8; j++) {
            float s = q[i][0] * k[j][0] + q[i][1] * k[j][1];
            #pragma unroll
            for (int o = 16; o > 0; o >>= 1)
                s += __shfl_xor_sync(0xffffffffu, s, o);
            p[i][j] = s * scale;
        }
    }

    #pragma unroll
    for (int i = 0; i < 8; i++) {
        float mx = p[i][0];
        #pragma unroll
        for (int j = 1; j < 8; j++)
            if (j <= i) mx = fmaxf(mx, p[i][j]);
        float sum = 0.0f;
        #pragma unroll
        for (int j = 0; j < 8; j++) {
            if (j <= i) { float e = __expf(p[i][j] - mx); p[i][j] = e; sum += e; }
            else          p[i][j] = 0.0f;
        }
        float inv = 1.0f / sum;
        #pragma unroll
        for (int j = 0; j < 8; j++) p[i][j] *= inv;
    }

    const size_t obase = (size_t)win * 8 * CDIM + head * HDIM;
    #pragma unroll
    for (int i = 0; i < 8; i++) {
        #pragma unroll
        for (int ld = 0; ld < 2; ld++) {
            float a = 0.0f;
            #pragma unroll
            for (int j = 0; j < 8; j++)
                a = fmaf(p[i][j], v[j][ld], a);
            out_h[obase + i * CDIM + ld * 32 + lane] = __float2half_rn(a);
        }
    }
}

// ---------------------------------------------------------------------------
// Launch
// ---------------------------------------------------------------------------
extern "C" void kernel_launch(void* const* d_in, const int* in_sizes, int n_in,
                              void* d_out, int out_size)
{
    const float* x      = (const float*)d_in[0];
    const float* w_qkv  = (const float*)d_in[1];
    const float* b_qkv  = (const float*)d_in[2];
    const float* w_proj = (const float*)d_in[3];
    const float* b_proj = (const float*)d_in[4];
    float* out = (float*)d_out;

    float* qkv_buf;
    __half *xh, *ath, *wqh, *wql, *wph, *wpl;
    cudaGetSymbolAddress((void**)&qkv_buf, g_qkv);
    cudaGetSymbolAddress((void**)&xh,  g_xh);
    cudaGetSymbolAddress((void**)&ath, g_ath);
    cudaGetSymbolAddress((void**)&wqh, g_wqh);
    cudaGetSymbolAddress((void**)&wql, g_wql);
    cudaGetSymbolAddress((void**)&wph, g_wph);
    cudaGetSymbolAddress((void**)&wpl, g_wpl);

    cudaFuncSetAttribute(gemm_tc, cudaFuncAttributeMaxDynamicSharedMemorySize,
                         GEMM_SMEM);

    // Converts: x -> fp16; weights -> fp16 hi/lo
    convert_h<<<(TOKENS * CDIM / 4) / 256, 256>>>(x, xh, TOKENS * CDIM / 4);
    convert_split<<<(QKVDIM * CDIM / 4) / 256, 256>>>(w_qkv, wqh, wql,
                                                      QKVDIM * CDIM / 4);
    convert_split<<<(CDIM * CDIM / 4) / 256, 256>>>(w_proj, wph, wpl,
                                                    CDIM * CDIM / 4);

    // K1: qkv = x @ w_qkv^T + b_qkv   (M=131072, N=768, K=256)
    {
        const int gx = QKVDIM / BN;              // 6
        const int ntiles = gx * (TOKENS / BM);   // 12288
        gemm_tc<<<GEMM_GRID, 256, GEMM_SMEM>>>(xh, wqh, wql, b_qkv,
                                               qkv_buf, QKVDIM, ntiles, gx);
    }

    // K2: windowed causal attention -> fp16
    attn_window_kernel<<<(NWIN * NHEAD) / 8, 256>>>(qkv_buf, ath);

    // K3: out = att @ w_proj^T + b_proj  (M=131072, N=256, K=256)
    {
        const int gx = CDIM / BN;                // 2
        const int ntiles = gx * (TOKENS / BM);   // 4096
        gemm_tc<<<GEMM_GRID, 256, GEMM_SMEM>>>(ath, wph, wpl, b_proj,
                                               out, CDIM, ntiles, gx);
    }
}

// round 15
// speedup vs baseline: 5.5871x; 1.0582x over previous
#include <cuda_runtime.h>
#include <cuda_fp16.h>
#include <cstdint>

// ---------------------------------------------------------------------------
// Problem constants
// ---------------------------------------------------------------------------
#define TOKENS   131072      // 32 * 4096
#define CDIM     256
#define QKVDIM   768
#define NWIN     16384
#define NHEAD    4
#define HDIM     64

// ---------------------------------------------------------------------------
// Scratch (device globals — no runtime allocation allowed)
// ---------------------------------------------------------------------------
__device__ float g_qkv[(size_t)TOKENS * QKVDIM];  // fp32 qkv
__device__ __align__(16) __half g_xh [(size_t)TOKENS * CDIM];   // fp16(x)
__device__ __align__(16) __half g_ath[(size_t)TOKENS * CDIM];   // fp16(att)
__device__ __align__(16) __half g_wqh[(size_t)QKVDIM * CDIM];
__device__ __align__(16) __half g_wql[(size_t)QKVDIM * CDIM];
__device__ __align__(16) __half g_wph[(size_t)CDIM * CDIM];
__device__ __align__(16) __half g_wpl[(size_t)CDIM * CDIM];

// ---------------------------------------------------------------------------
// Low-level helpers (sm_80-era ISA only: ldmatrix / mma.sync / cp.async)
// ---------------------------------------------------------------------------
__device__ __forceinline__ uint32_t smem_to_u32(const void* p) {
    uint32_t a;
    asm("{ .reg .u64 t; cvta.to.shared.u64 t, %1; cvt.u32.u64 %0, t; }"
        : "=r"(a) : "l"(p));
    return a;
}

__device__ __forceinline__ void cp_async16(uint32_t dst, const void* src) {
    asm volatile("cp.async.cg.shared.global [%0], [%1], 16;"
                 :: "r"(dst), "l"(src));
}
__device__ __forceinline__ void cp_commit() {
    asm volatile("cp.async.commit_group;");
}
template <int N>
__device__ __forceinline__ void cp_wait() {
    asm volatile("cp.async.wait_group %0;" :: "n"(N));
}

__device__ __forceinline__ void ldmx4(uint32_t* r, uint32_t addr) {
    asm volatile("ldmatrix.sync.aligned.m8n8.x4.shared.b16 {%0,%1,%2,%3}, [%4];"
                 : "=r"(r[0]), "=r"(r[1]), "=r"(r[2]), "=r"(r[3]) : "r"(addr));
}

__device__ __forceinline__ void mma_f16(float* d, const uint32_t* a,
                                        uint32_t b0, uint32_t b1) {
    asm volatile(
        "mma.sync.aligned.m16n8k16.row.col.f32.f16.f16.f32 "
        "{%0,%1,%2,%3}, {%4,%5,%6,%7}, {%8,%9}, {%0,%1,%2,%3};"
        : "+f"(d[0]), "+f"(d[1]), "+f"(d[2]), "+f"(d[3])
        : "r"(a[0]), "r"(a[1]), "r"(a[2]), "r"(a[3]), "r"(b0), "r"(b1));
}

#define SMEM_SWIZZLE_128B(off) ((off) ^ (((off) >> 3) & 0x70))

// ---------------------------------------------------------------------------
// Converts: fp32 -> fp16 (A side), fp32 -> (hi, lo) fp16 pair (B side)
// ---------------------------------------------------------------------------
__global__ __launch_bounds__(256) void convert_h(
    const float* __restrict__ src, __half* __restrict__ dst, int n4)
{
    int i = blockIdx.x * blockDim.x + threadIdx.x;
    if (i >= n4) return;
    float4 v = reinterpret_cast<const float4*>(src)[i];
    __half2* p = reinterpret_cast<__half2*>(dst + (size_t)i * 4);
    p[0] = __floats2half2_rn(v.x, v.y);
    p[1] = __floats2half2_rn(v.z, v.w);
}

__global__ __launch_bounds__(256) void convert_split(
    const float* __restrict__ src,
    __half* __restrict__ hi, __half* __restrict__ lo, int n4)
{
    int i = blockIdx.x * blockDim.x + threadIdx.x;
    if (i >= n4) return;
    float4 v = reinterpret_cast<const float4*>(src)[i];
    float f[4] = {v.x, v.y, v.z, v.w};
    __half h[4], l[4];
    #pragma unroll
    for (int j = 0; j < 4; j++) {
        h[j] = __float2half_rn(f[j]);
        l[j] = __float2half_rn(f[j] - __half2float(h[j]));
    }
    __half2* ph = reinterpret_cast<__half2*>(hi + (size_t)i * 4);
    __half2* pl = reinterpret_cast<__half2*>(lo + (size_t)i * 4);
    ph[0] = __halves2half2(h[0], h[1]);
    ph[1] = __halves2half2(h[2], h[3]);
    pl[0] = __halves2half2(l[0], l[1]);
    pl[1] = __halves2half2(l[2], l[3]);
}

// ---------------------------------------------------------------------------
// Persistent HMMA GEMM: C[M,Ntot] = A[M,256] @ (Bh+Bl)[Ntot,256]^T + bias
// A single fp16, B 2-term fp16 split -> 2 MMAs per (k16, 16x8) tile.
// CTA 128x128, 8 warps (2m x 4n), warp tile 64x32 (4 mi) -> 128 B LDSM/MMA.
// K-tiles of 64 (128B SW128-swizzled rows), cp.async double-buffered with the
// pipeline continuous across tile boundaries (persistent CTAs, 2/SM).
// ---------------------------------------------------------------------------
#define BM 128
#define BN 128
#define KT 64
#define NKT 4                        // 256 / 64
#define A_BUF 16384                  // 128 rows * 128 B
#define B_BUF 16384                  // 128 rows * 128 B
#define STAGE_BYTES (A_BUF + 2 * B_BUF)       // A, Bh, Bl = 49152
#define GEMM_SMEM   (2 * STAGE_BYTES)         // 98304
#define GEMM_GRID   304              // 2 CTAs/SM * 152 SMs (GB300)

static __device__ __forceinline__ void stage_load(
    uint32_t su, int stage, int tid,
    const __half* __restrict__ aH,
    const __half* __restrict__ bH, const __half* __restrict__ bL)
{
    const uint32_t sbase = su + stage * STAGE_BYTES;
    const __half* srcs[3] = {aH, bH, bL};
    #pragma unroll
    for (int b = 0; b < 3; b++) {
        const __half* s = srcs[b];
        uint32_t dbase = sbase + b * A_BUF;
        #pragma unroll
        for (int i = 0; i < 4; i++) {
            int id  = tid + i * 256;          // 0..1023 (128 rows x 8 chunks)
            int row = id >> 3, ch = id & 7;
            uint32_t off = SMEM_SWIZZLE_128B((uint32_t)(row * 128 + ch * 16));
            cp_async16(dbase + off, s + (size_t)row * CDIM + ch * 8);
        }
    }
}

__global__ __launch_bounds__(256, 2) void gemm_tc(
    const __half* __restrict__ Ah,
    const __half* __restrict__ Bh, const __half* __restrict__ Bl,
    const float* __restrict__ bias, float* __restrict__ C,
    int Ntot, int ntiles, int gx)
{
    extern __shared__ __align__(128) char sb[];
    const uint32_t su = smem_to_u32(sb);

    const int tid    = threadIdx.x;
    const int wid    = tid >> 5;
    const int lane   = tid & 31;
    const int warp_m = wid & 1;      // 0..1 -> 64-row slab
    const int warp_n = wid >> 1;     // 0..3 -> 32-col slab
    const int nct    = (int)gridDim.x;

    // ldmatrix per-lane addressing: swizzle XOR (row&7) applied to the FINAL
    // 16B-chunk index (ch0 + 2*kk) inside the unrolled k loop. mi/g offsets
    // move by 16 rows -> row&7 invariant.
    const int aRow = warp_m * 64 + (lane & 15);
    const int aCh0 = lane >> 4;              // 0,1
    const uint32_t aXor    = (uint32_t)(aRow & 7);
    const uint32_t aRowOff = (uint32_t)aRow * 128;
    const int bRow = warp_n * 32 + (lane & 7) + ((lane >> 4) << 3);
    const int bCh0 = (lane >> 3) & 1;        // 0,1
    const uint32_t bXor    = (uint32_t)(bRow & 7);
    const uint32_t bRowOff = (uint32_t)bRow * 128;

    int tile = blockIdx.x;
    if (tile >= ntiles) return;

    // Preload k-tile 0 of the first tile into stage 0.
    {
        const size_t aOff = (size_t)(tile / gx) * BM * CDIM;
        const size_t bOff = (size_t)(tile % gx) * BN * CDIM;
        stage_load(su, 0, tid, Ah + aOff, Bh + bOff, Bl + bOff);
        cp_commit();
    }
    int parity = 0;

    for (; tile < ntiles; tile += nct) {
        const int brow = (tile / gx) * BM;
        const int bcol = (tile % gx) * BN;
        const __half* aH = Ah + (size_t)brow * CDIM;
        const __half* bH = Bh + (size_t)bcol * CDIM;
        const __half* bL = Bl + (size_t)bcol * CDIM;

        const int nextTile = tile + nct;
        const bool hasNext = nextTile < ntiles;
        const size_t naOff = hasNext ? (size_t)(nextTile / gx) * BM * CDIM : 0;
        const size_t nbOff = hasNext ? (size_t)(nextTile % gx) * BN * CDIM : 0;

        float acc[4][4][4];
        #pragma unroll
        for (int mi = 0; mi < 4; mi++)
            #pragma unroll
            for (int ni = 0; ni < 4; ni++)
                #pragma unroll
                for (int j = 0; j < 4; j++) acc[mi][ni][j] = 0.0f;

        #pragma unroll
        for (int t = 0; t < NKT; t++) {
            // Issue the NEXT chunk (next k-tile, or next tile's k0) into the
            // other stage, keeping the cp.async stream continuous.
            if (t + 1 < NKT) {
                stage_load(su, parity ^ 1, tid,
                           aH + (t + 1) * KT, bH + (t + 1) * KT,
                           bL + (t + 1) * KT);
                cp_commit();
                cp_wait<1>();
            } else if (hasNext) {
                stage_load(su, parity ^ 1, tid,
                           Ah + naOff, Bh + nbOff, Bl + nbOff);
                cp_commit();
                cp_wait<1>();
            } else {
                cp_wait<0>();
            }
            __syncthreads();

            const uint32_t sA  = su + parity * STAGE_BYTES;
            const uint32_t sB  = sA + A_BUF;
            const uint32_t sBl = sB + B_BUF;

            #pragma unroll
            for (int kk = 0; kk < 4; kk++) {       // k16 steps within K-tile
                const uint32_t aOff =
                    aRowOff + ((((uint32_t)(aCh0 + 2 * kk)) ^ aXor) << 4);
                const uint32_t bOff =
                    bRowOff + ((((uint32_t)(bCh0 + 2 * kk)) ^ bXor) << 4);
                uint32_t ah[4][4];
                #pragma unroll
                for (int mi = 0; mi < 4; mi++)
                    ldmx4(ah[mi], sA + aOff + mi * 2048);
                // Process B one n16 group at a time (keeps live regs low).
                #pragma unroll
                for (int g = 0; g < 2; g++) {
                    uint32_t bh[4], bl[4];
                    ldmx4(bh, sB  + bOff + g * 2048);
                    ldmx4(bl, sBl + bOff + g * 2048);
                    #pragma unroll
                    for (int ni2 = 0; ni2 < 2; ni2++) {   // two n8 within group
                        const int ni = g * 2 + ni2;
                        const int p  = ni2 * 2;
                        #pragma unroll
                        for (int mi = 0; mi < 4; mi++) {
                            mma_f16(acc[mi][ni], ah[mi], bh[p], bh[p + 1]);
                            mma_f16(acc[mi][ni], ah[mi], bl[p], bl[p + 1]);
                        }
                    }
                }
            }
            __syncthreads();   // stage `parity` free for the next issue
            parity ^= 1;
        }

        // Epilogue (overlaps next tile's k0 cp.async already in flight).
        #pragma unroll
        for (int mi = 0; mi < 4; mi++) {
            const int r0 = brow + warp_m * 64 + mi * 16 + (lane >> 2);
            #pragma unroll
            for (int ni = 0; ni < 4; ni++) {
                const int col = bcol + warp_n * 32 + ni * 8 + (lane & 3) * 2;
                const float b0 = bias[col], b1 = bias[col + 1];
                float2 v0 = {acc[mi][ni][0] + b0, acc[mi][ni][1] + b1};
                float2 v1 = {acc[mi][ni][2] + b0, acc[mi][ni][3] + b1};
                *reinterpret_cast<float2*>(&C[(size_t)r0 * Ntot + col]) = v0;
                *reinterpret_cast<float2*>(&C[(size_t)(r0 + 8) * Ntot + col]) = v1;
            }
        }
    }
}

// ---------------------------------------------------------------------------
// Windowed causal attention: one warp per (window, head). Reads fp32 qkv,
// writes fp16 directly (feeds GEMM3 A operand).
// ---------------------------------------------------------------------------
__global__ __launch_bounds__(256) void attn_window_kernel(
    const float* __restrict__ qkv, __half* __restrict__ out_h)
{
    const int warp_global = blockIdx.x * 8 + (threadIdx.x >> 5);
    const int lane = threadIdx.x & 31;
    const int win  = warp_global >> 2;
    const int head = warp_global & 3;
    const float scale = 0.125f;

    const float* base = qkv + (size_t)win * 8 * QKVDIM + head * HDIM;

    float q[8][2], k[8][2], v[8][2];
    #pragma unroll
    for (int i = 0; i < 8; i++) {
        #pragma unroll
        for (int ld = 0; ld < 2; ld++) {
            int d = ld * 32 + lane;
            q[i][ld] = base[i * QKVDIM + d];
            k[i][ld] = base[i * QKVDIM + 256 + d];
            v[i][ld] = base[i * QKVDIM + 512 + d];
        }
    }

    float p[8][8];
    #pragma unroll
    for (int i = 0; i < 8; i++) {
        #pragma unroll
        for (int j = 0; j < 8; j++) {
            float s = q[i][0] * k[j][0] + q[i][1] * k[j][1];
            #pragma unroll
            for (int o = 16; o > 0; o >>= 1)
                s += __shfl_xor_sync(0xffffffffu, s, o);
            p[i][j] = s * scale;
        }
    }

    #pragma unroll
    for (int i = 0; i < 8; i++) {
        float mx = p[i][0];
        #pragma unroll
        for (int j = 1; j < 8; j++)
            if (j <= i) mx = fmaxf(mx, p[i][j]);
        float sum = 0.0f;
        #pragma unroll
        for (int j = 0; j < 8; j++) {
            if (j <= i) { float e = __expf(p[i][j] - mx); p[i][j] = e; sum += e; }
            else          p[i][j] = 0.0f;
        }
        float inv = 1.0f / sum;
        #pragma unroll
        for (int j = 0; j < 8; j++) p[i][j] *= inv;
    }

    const size_t obase = (size_t)win * 8 * CDIM + head * HDIM;
    #pragma unroll
    for (int i = 0; i < 8; i++) {
        #pragma unroll
        for (int ld = 0; ld < 2; ld++) {
            float a = 0.0f;
            #pragma unroll
            for (int j = 0; j < 8; j++)
                a = fmaf(p[i][j], v[j][ld], a);
            out_h[obase + i * CDIM + ld * 32 + lane] = __float2half_rn(a);
        }
    }
}

// ---------------------------------------------------------------------------
// Launch
// ---------------------------------------------------------------------------
extern "C" void kernel_launch(void* const* d_in, const int* in_sizes, int n_in,
                              void* d_out, int out_size)
{
    const float* x      = (const float*)d_in[0];
    const float* w_qkv  = (const float*)d_in[1];
    const float* b_qkv  = (const float*)d_in[2];
    const float* w_proj = (const float*)d_in[3];
    const float* b_proj = (const float*)d_in[4];
    float* out = (float*)d_out;

    float* qkv_buf;
    __half *xh, *ath, *wqh, *wql, *wph, *wpl;
    cudaGetSymbolAddress((void**)&qkv_buf, g_qkv);
    cudaGetSymbolAddress((void**)&xh,  g_xh);
    cudaGetSymbolAddress((void**)&ath, g_ath);
    cudaGetSymbolAddress((void**)&wqh, g_wqh);
    cudaGetSymbolAddress((void**)&wql, g_wql);
    cudaGetSymbolAddress((void**)&wph, g_wph);
    cudaGetSymbolAddress((void**)&wpl, g_wpl);

    cudaFuncSetAttribute(gemm_tc, cudaFuncAttributeMaxDynamicSharedMemorySize,
                         GEMM_SMEM);

    // Converts: x -> fp16; weights -> fp16 hi/lo
    convert_h<<<(TOKENS * CDIM / 4) / 256, 256>>>(x, xh, TOKENS * CDIM / 4);
    convert_split<<<(QKVDIM * CDIM / 4) / 256, 256>>>(w_qkv, wqh, wql,
                                                      QKVDIM * CDIM / 4);
    convert_split<<<(CDIM * CDIM / 4) / 256, 256>>>(w_proj, wph, wpl,
                                                    CDIM * CDIM / 4);

    // K1: qkv = x @ w_qkv^T + b_qkv   (M=131072, N=768, K=256)
    {
        const int gx = QKVDIM / BN;              // 6
        const int ntiles = gx * (TOKENS / BM);   // 6144
        gemm_tc<<<GEMM_GRID, 256, GEMM_SMEM>>>(xh, wqh, wql, b_qkv,
                                               qkv_buf, QKVDIM, ntiles, gx);
    }

    // K2: windowed causal attention -> fp16
    attn_window_kernel<<<(NWIN * NHEAD) / 8, 256>>>(qkv_buf, ath);

    // K3: out = att @ w_proj^T + b_proj  (M=131072, N=256, K=256)
    {
        const int gx = CDIM / BN;                // 2
        const int ntiles = gx * (TOKENS / BM);   // 2048
        gemm_tc<<<GEMM_GRID, 256, GEMM_SMEM>>>(ath, wph, wpl, b_proj,
                                               out, CDIM, ntiles, gx);
    }
}

// round 16
// speedup vs baseline: 7.4624x; 1.3356x over previous
#include <cuda_runtime.h>
#include <cuda_fp16.h>
#include <cstdint>

// ---------------------------------------------------------------------------
// Problem constants
// ---------------------------------------------------------------------------
#define TOKENS   131072      // 32 * 4096
#define CDIM     256
#define QKVDIM   768
#define NWIN     16384
#define NHEAD    4
#define HDIM     64

// ---------------------------------------------------------------------------
// Scratch (device globals — no runtime allocation allowed)
// ---------------------------------------------------------------------------
__device__ __align__(16) __half g_qkv[(size_t)TOKENS * QKVDIM];  // fp16 qkv
__device__ __align__(16) __half g_xh [(size_t)TOKENS * CDIM];    // fp16(x)
__device__ __align__(16) __half g_ath[(size_t)TOKENS * CDIM];    // fp16(att)
__device__ __align__(16) __half g_wqh[(size_t)QKVDIM * CDIM];
__device__ __align__(16) __half g_wph[(size_t)CDIM * CDIM];

// ---------------------------------------------------------------------------
// Low-level helpers (sm_80-era ISA only: ldmatrix / mma.sync / cp.async)
// ---------------------------------------------------------------------------
__device__ __forceinline__ uint32_t smem_to_u32(const void* p) {
    uint32_t a;
    asm("{ .reg .u64 t; cvta.to.shared.u64 t, %1; cvt.u32.u64 %0, t; }"
        : "=r"(a) : "l"(p));
    return a;
}

__device__ __forceinline__ void cp_async16(uint32_t dst, const void* src) {
    asm volatile("cp.async.cg.shared.global [%0], [%1], 16;"
                 :: "r"(dst), "l"(src));
}
__device__ __forceinline__ void cp_commit() {
    asm volatile("cp.async.commit_group;");
}
template <int N>
__device__ __forceinline__ void cp_wait() {
    asm volatile("cp.async.wait_group %0;" :: "n"(N));
}

__device__ __forceinline__ void ldmx4(uint32_t* r, uint32_t addr) {
    asm volatile("ldmatrix.sync.aligned.m8n8.x4.shared.b16 {%0,%1,%2,%3}, [%4];"
                 : "=r"(r[0]), "=r"(r[1]), "=r"(r[2]), "=r"(r[3]) : "r"(addr));
}

__device__ __forceinline__ void mma_f16(float* d, const uint32_t* a,
                                        uint32_t b0, uint32_t b1) {
    asm volatile(
        "mma.sync.aligned.m16n8k16.row.col.f32.f16.f16.f32 "
        "{%0,%1,%2,%3}, {%4,%5,%6,%7}, {%8,%9}, {%0,%1,%2,%3};"
        : "+f"(d[0]), "+f"(d[1]), "+f"(d[2]), "+f"(d[3])
        : "r"(a[0]), "r"(a[1]), "r"(a[2]), "r"(a[3]), "r"(b0), "r"(b1));
}

#define SMEM_SWIZZLE_128B(off) ((off) ^ (((off) >> 3) & 0x70))

// ---------------------------------------------------------------------------
// Convert: fp32 -> fp16
// ---------------------------------------------------------------------------
__global__ __launch_bounds__(256) void convert_h(
    const float* __restrict__ src, __half* __restrict__ dst, int n4)
{
    int i = blockIdx.x * blockDim.x + threadIdx.x;
    if (i >= n4) return;
    float4 v = reinterpret_cast<const float4*>(src)[i];
    __half2* p = reinterpret_cast<__half2*>(dst + (size_t)i * 4);
    p[0] = __floats2half2_rn(v.x, v.y);
    p[1] = __floats2half2_rn(v.z, v.w);
}

// ---------------------------------------------------------------------------
// Persistent plain-fp16 HMMA GEMM: C[M,Ntot] = A[M,256] @ B[Ntot,256]^T + bias
// CTA 128x128, 8 warps (2m x 4n), warp tile 64x32, mma.m16n8k16 f16.
// K-chunks of 64 (128B SW128-swizzled rows). 3-stage cp.async pipeline
// running continuously across k-chunks AND tile boundaries (persistent CTAs,
// 2/SM). Templated output type (fp16 for qkv, fp32 for final out).
// ---------------------------------------------------------------------------
#define BM 128
#define BN 128
#define KT 64
#define NKT 4                        // 256 / 64
#define A_BUF 16384                  // 128 rows * 128 B
#define STAGE_BYTES (2 * A_BUF)      // A + B = 32768
#define NSTAGE 3
#define GEMM_SMEM   (NSTAGE * STAGE_BYTES)    // 98304
#define GEMM_GRID   304              // 2 CTAs/SM * 152 SMs (GB300)

static __device__ __forceinline__ void stage_load(
    uint32_t su, int stage, int tid,
    const __half* __restrict__ aP, const __half* __restrict__ bP)
{
    const uint32_t sbase = su + stage * STAGE_BYTES;
    const __half* srcs[2] = {aP, bP};
    #pragma unroll
    for (int b = 0; b < 2; b++) {
        const __half* s = srcs[b];
        uint32_t dbase = sbase + b * A_BUF;
        #pragma unroll
        for (int i = 0; i < 4; i++) {
            int id  = tid + i * 256;          // 0..1023 (128 rows x 8 chunks)
            int row = id >> 3, ch = id & 7;
            uint32_t off = SMEM_SWIZZLE_128B((uint32_t)(row * 128 + ch * 16));
            cp_async16(dbase + off, s + (size_t)row * CDIM + ch * 8);
        }
    }
}

template <typename OutT>
__global__ __launch_bounds__(256, 2) void gemm_tc(
    const __half* __restrict__ Ah, const __half* __restrict__ Bh,
    const float* __restrict__ bias, OutT* __restrict__ C,
    int Ntot, int ntiles, int gx)
{
    extern __shared__ __align__(128) char sb[];
    const uint32_t su = smem_to_u32(sb);

    const int tid    = threadIdx.x;
    const int wid    = tid >> 5;
    const int lane   = tid & 31;
    const int warp_m = wid & 1;      // 0..1 -> 64-row slab
    const int warp_n = wid >> 1;     // 0..3 -> 32-col slab
    const int nct    = (int)gridDim.x;
    const int tile0  = blockIdx.x;
    if (tile0 >= ntiles) return;

    // ldmatrix per-lane addressing: swizzle XOR (row&7) applied to the FINAL
    // 16B-chunk index (ch0 + 2*kk) inside the unrolled k loop. mi/g offsets
    // move by 16 rows -> row&7 invariant.
    const int aRow = warp_m * 64 + (lane & 15);
    const int aCh0 = lane >> 4;              // 0,1
    const uint32_t aXor    = (uint32_t)(aRow & 7);
    const uint32_t aRowOff = (uint32_t)aRow * 128;
    const int bRow = warp_n * 32 + (lane & 7) + ((lane >> 4) << 3);
    const int bCh0 = (lane >> 3) & 1;        // 0,1
    const uint32_t bXor    = (uint32_t)(bRow & 7);
    const uint32_t bRowOff = (uint32_t)bRow * 128;

    // This CTA's flattened chunk stream: chunk c -> (tile, k-chunk).
    const int nTilesMine = (ntiles - tile0 + nct - 1) / nct;
    const int total = nTilesMine * NKT;

    auto chunk_ptrs = [&](int c, const __half*& aP, const __half*& bP) {
        const int tl = tile0 + (c >> 2) * nct;
        const int kt = c & 3;
        aP = Ah + (size_t)(tl / gx) * BM * CDIM + kt * KT;
        bP = Bh + (size_t)(tl % gx) * BN * CDIM + kt * KT;
    };

    // Prologue: fill 2 stages.
    {
        const __half *aP, *bP;
        chunk_ptrs(0, aP, bP);
        stage_load(su, 0, tid, aP, bP);
        cp_commit();
        if (total > 1) {
            chunk_ptrs(1, aP, bP);
            stage_load(su, 1, tid, aP, bP);
            cp_commit();
        }
    }

    float acc[4][4][4];

    for (int c = 0; c < total; c++) {
        // Keep the cp.async stream 2 chunks ahead.
        if (c + 2 < total) {
            const __half *aP, *bP;
            chunk_ptrs(c + 2, aP, bP);
            stage_load(su, (c + 2) % NSTAGE, tid, aP, bP);
            cp_commit();
            cp_wait<2>();
        } else if (c + 1 < total) {
            cp_wait<1>();
        } else {
            cp_wait<0>();
        }
        __syncthreads();          // chunk c's data visible to all warps

        if ((c & 3) == 0) {
            #pragma unroll
            for (int mi = 0; mi < 4; mi++)
                #pragma unroll
                for (int ni = 0; ni < 4; ni++)
                    #pragma unroll
                    for (int j = 0; j < 4; j++) acc[mi][ni][j] = 0.0f;
        }

        const uint32_t sA = su + (c % NSTAGE) * STAGE_BYTES;
        const uint32_t sB = sA + A_BUF;

        #pragma unroll
        for (int kk = 0; kk < 4; kk++) {       // k16 steps within chunk
            const uint32_t aOff =
                aRowOff + ((((uint32_t)(aCh0 + 2 * kk)) ^ aXor) << 4);
            const uint32_t bOff =
                bRowOff + ((((uint32_t)(bCh0 + 2 * kk)) ^ bXor) << 4);
            uint32_t ah[4][4];
            #pragma unroll
            for (int mi = 0; mi < 4; mi++)
                ldmx4(ah[mi], sA + aOff + mi * 2048);
            #pragma unroll
            for (int g = 0; g < 2; g++) {      // n16 groups
                uint32_t bh[4];
                ldmx4(bh, sB + bOff + g * 2048);
                #pragma unroll
                for (int ni2 = 0; ni2 < 2; ni2++) {
                    const int ni = g * 2 + ni2;
                    const int p  = ni2 * 2;
                    #pragma unroll
                    for (int mi = 0; mi < 4; mi++)
                        mma_f16(acc[mi][ni], ah[mi], bh[p], bh[p + 1]);
                }
            }
        }

        if ((c & 3) == 3) {
            // Epilogue for the finished tile (overlaps in-flight loads).
            const int tl   = tile0 + (c >> 2) * nct;
            const int brow = (tl / gx) * BM;
            const int bcol = (tl % gx) * BN;
            #pragma unroll
            for (int mi = 0; mi < 4; mi++) {
                const int r0 = brow + warp_m * 64 + mi * 16 + (lane >> 2);
                #pragma unroll
                for (int ni = 0; ni < 4; ni++) {
                    const int col = bcol + warp_n * 32 + ni * 8 + (lane & 3) * 2;
                    const float b0 = bias[col], b1 = bias[col + 1];
                    if constexpr (sizeof(OutT) == 2) {
                        __half2 v0 = __floats2half2_rn(acc[mi][ni][0] + b0,
                                                       acc[mi][ni][1] + b1);
                        __half2 v1 = __floats2half2_rn(acc[mi][ni][2] + b0,
                                                       acc[mi][ni][3] + b1);
                        *reinterpret_cast<__half2*>(
                            &C[(size_t)r0 * Ntot + col]) = v0;
                        *reinterpret_cast<__half2*>(
                            &C[(size_t)(r0 + 8) * Ntot + col]) = v1;
                    } else {
                        float2 v0 = {acc[mi][ni][0] + b0, acc[mi][ni][1] + b1};
                        float2 v1 = {acc[mi][ni][2] + b0, acc[mi][ni][3] + b1};
                        *reinterpret_cast<float2*>(
                            &C[(size_t)r0 * Ntot + col]) = v0;
                        *reinterpret_cast<float2*>(
                            &C[(size_t)(r0 + 8) * Ntot + col]) = v1;
                    }
                }
            }
        }
        __syncthreads();   // all warps done with stage c%NSTAGE -> reusable
    }
}

// ---------------------------------------------------------------------------
// Windowed causal attention: one warp per (window, head). Reads fp16 qkv,
// writes fp16 att directly (feeds GEMM3 A operand).
// ---------------------------------------------------------------------------
__global__ __launch_bounds__(256) void attn_window_kernel(
    const __half* __restrict__ qkv, __half* __restrict__ out_h)
{
    const int warp_global = blockIdx.x * 8 + (threadIdx.x >> 5);
    const int lane = threadIdx.x & 31;
    const int win  = warp_global >> 2;
    const int head = warp_global & 3;
    const float scale = 0.125f;

    const __half* base = qkv + (size_t)win * 8 * QKVDIM + head * HDIM;

    float q[8][2], k[8][2], v[8][2];
    #pragma unroll
    for (int i = 0; i < 8; i++) {
        #pragma unroll
        for (int ld = 0; ld < 2; ld++) {
            int d = ld * 32 + lane;
            q[i][ld] = __half2float(base[i * QKVDIM + d]);
            k[i][ld] = __half2float(base[i * QKVDIM + 256 + d]);
            v[i][ld] = __half2float(base[i * QKVDIM + 512 + d]);
        }
    }

    float p[8][8];
    #pragma unroll
    for (int i = 0; i < 8; i++) {
        #pragma unroll
        for (int j = 0; j < 8; j++) {
            float s = q[i][0] * k[j][0] + q[i][1] * k[j][1];
            #pragma unroll
            for (int o = 16; o > 0; o >>= 1)
                s += __shfl_xor_sync(0xffffffffu, s, o);
            p[i][j] = s * scale;
        }
    }

    #pragma unroll
    for (int i = 0; i < 8; i++) {
        float mx = p[i][0];
        #pragma unroll
        for (int j = 1; j < 8; j++)
            if (j <= i) mx = fmaxf(mx, p[i][j]);
        float sum = 0.0f;
        #pragma unroll
        for (int j = 0; j < 8; j++) {
            if (j <= i) { float e = __expf(p[i][j] - mx); p[i][j] = e; sum += e; }
            else          p[i][j] = 0.0f;
        }
        float inv = 1.0f / sum;
        #pragma unroll
        for (int j = 0; j < 8; j++) p[i][j] *= inv;
    }

    const size_t obase = (size_t)win * 8 * CDIM + head * HDIM;
    #pragma unroll
    for (int i = 0; i < 8; i++) {
        #pragma unroll
        for (int ld = 0; ld < 2; ld++) {
            float a = 0.0f;
            #pragma unroll
            for (int j = 0; j < 8; j++)
                a = fmaf(p[i][j], v[j][ld], a);
            out_h[obase + i * CDIM + ld * 32 + lane] = __float2half_rn(a);
        }
    }
}

// ---------------------------------------------------------------------------
// Launch
// ---------------------------------------------------------------------------
extern "C" void kernel_launch(void* const* d_in, const int* in_sizes, int n_in,
                              void* d_out, int out_size)
{
    const float* x      = (const float*)d_in[0];
    const float* w_qkv  = (const float*)d_in[1];
    const float* b_qkv  = (const float*)d_in[2];
    const float* w_proj = (const float*)d_in[3];
    const float* b_proj = (const float*)d_in[4];
    float* out = (float*)d_out;

    __half *qkv_buf, *xh, *ath, *wqh, *wph;
    cudaGetSymbolAddress((void**)&qkv_buf, g_qkv);
    cudaGetSymbolAddress((void**)&xh,  g_xh);
    cudaGetSymbolAddress((void**)&ath, g_ath);
    cudaGetSymbolAddress((void**)&wqh, g_wqh);
    cudaGetSymbolAddress((void**)&wph, g_wph);

    cudaFuncSetAttribute(gemm_tc<__half>,
                         cudaFuncAttributeMaxDynamicSharedMemorySize, GEMM_SMEM);
    cudaFuncSetAttribute(gemm_tc<float>,
                         cudaFuncAttributeMaxDynamicSharedMemorySize, GEMM_SMEM);

    // Converts: x, weights -> fp16
    convert_h<<<(TOKENS * CDIM / 4) / 256, 256>>>(x, xh, TOKENS * CDIM / 4);
    convert_h<<<(QKVDIM * CDIM / 4) / 256, 256>>>(w_qkv, wqh, QKVDIM * CDIM / 4);
    convert_h<<<(CDIM * CDIM / 4) / 256, 256>>>(w_proj, wph, CDIM * CDIM / 4);

    // K1: qkv = x @ w_qkv^T + b_qkv   (M=131072, N=768, K=256) -> fp16
    {
        const int gx = QKVDIM / BN;              // 6
        const int ntiles = gx * (TOKENS / BM);   // 6144
        gemm_tc<__half><<<GEMM_GRID, 256, GEMM_SMEM>>>(
            xh, wqh, b_qkv, qkv_buf, QKVDIM, ntiles, gx);
    }

    // K2: windowed causal attention (fp16 in) -> fp16
    attn_window_kernel<<<(NWIN * NHEAD) / 8, 256>>>(qkv_buf, ath);

    // K3: out = att @ w_proj^T + b_proj  (M=131072, N=256, K=256) -> fp32
    {
        const int gx = CDIM / BN;                // 2
        const int ntiles = gx * (TOKENS / BM);   // 2048
        gemm_tc<float><<<GEMM_GRID, 256, GEMM_SMEM>>>(
            ath, wph, b_proj, out, CDIM, ntiles, gx);
    }
}

// round 17
// speedup vs baseline: 7.8408x; 1.0507x over previous
#include <cuda_runtime.h>
#include <cuda_fp16.h>
#include <cstdint>

// ---------------------------------------------------------------------------
// Problem constants
// ---------------------------------------------------------------------------
#define TOKENS   131072      // 32 * 4096
#define CDIM     256
#define QKVDIM   768
#define NWIN     16384
#define NHEAD    4
#define HDIM     64

// ---------------------------------------------------------------------------
// Scratch (device globals — no runtime allocation allowed)
// ---------------------------------------------------------------------------
__device__ __align__(16) __half g_qkv[(size_t)TOKENS * QKVDIM];  // fp16 qkv
__device__ __align__(16) __half g_xh [(size_t)TOKENS * CDIM];    // fp16(x)
__device__ __align__(16) __half g_ath[(size_t)TOKENS * CDIM];    // fp16(att)
__device__ __align__(16) __half g_wqh[(size_t)QKVDIM * CDIM];
__device__ __align__(16) __half g_wph[(size_t)CDIM * CDIM];

// ---------------------------------------------------------------------------
// Low-level helpers (sm_80-era ISA only: ldmatrix / mma.sync / cp.async)
// ---------------------------------------------------------------------------
__device__ __forceinline__ uint32_t smem_to_u32(const void* p) {
    uint32_t a;
    asm("{ .reg .u64 t; cvta.to.shared.u64 t, %1; cvt.u32.u64 %0, t; }"
        : "=r"(a) : "l"(p));
    return a;
}

__device__ __forceinline__ void cp_async16(uint32_t dst, const void* src) {
    asm volatile("cp.async.cg.shared.global [%0], [%1], 16;"
                 :: "r"(dst), "l"(src));
}
__device__ __forceinline__ void cp_commit() {
    asm volatile("cp.async.commit_group;");
}
template <int N>
__device__ __forceinline__ void cp_wait() {
    asm volatile("cp.async.wait_group %0;" :: "n"(N));
}

__device__ __forceinline__ void ldmx4(uint32_t* r, uint32_t addr) {
    asm volatile("ldmatrix.sync.aligned.m8n8.x4.shared.b16 {%0,%1,%2,%3}, [%4];"
                 : "=r"(r[0]), "=r"(r[1]), "=r"(r[2]), "=r"(r[3]) : "r"(addr));
}

__device__ __forceinline__ void mma_f16(float* d, const uint32_t* a,
                                        uint32_t b0, uint32_t b1) {
    asm volatile(
        "mma.sync.aligned.m16n8k16.row.col.f32.f16.f16.f32 "
        "{%0,%1,%2,%3}, {%4,%5,%6,%7}, {%8,%9}, {%0,%1,%2,%3};"
        : "+f"(d[0]), "+f"(d[1]), "+f"(d[2]), "+f"(d[3])
        : "r"(a[0]), "r"(a[1]), "r"(a[2]), "r"(a[3]), "r"(b0), "r"(b1));
}

#define SMEM_SWIZZLE_128B(off) ((off) ^ (((off) >> 3) & 0x70))

// ---------------------------------------------------------------------------
// Convert: fp32 -> fp16
// ---------------------------------------------------------------------------
__global__ __launch_bounds__(256) void convert_h(
    const float* __restrict__ src, __half* __restrict__ dst, int n4)
{
    int i = blockIdx.x * blockDim.x + threadIdx.x;
    if (i >= n4) return;
    float4 v = reinterpret_cast<const float4*>(src)[i];
    __half2* p = reinterpret_cast<__half2*>(dst + (size_t)i * 4);
    p[0] = __floats2half2_rn(v.x, v.y);
    p[1] = __floats2half2_rn(v.z, v.w);
}

// ---------------------------------------------------------------------------
// Persistent plain-fp16 HMMA GEMM: C[M,Ntot] = A[M,256] @ B[Ntot,256]^T + bias
// CTA 128x128, 8 warps (2m x 4n), warp tile 64x32, mma.m16n8k16 f16.
// K-chunks of 64 (128B SW128-swizzled rows). 3-stage cp.async pipeline,
// continuous across chunks AND tiles; ONE __syncthreads per chunk
// (wait<1> -> sync -> issue -> compute: arrival at the barrier proves the
// stage being overwritten was fully consumed last chunk). Div-free
// incremental tile walk. Templated output (fp16 qkv / fp32 final).
// ---------------------------------------------------------------------------
#define BM 128
#define BN 128
#define KT 64
#define A_BUF 16384                  // 128 rows * 128 B
#define STAGE_BYTES (2 * A_BUF)      // A + B = 32768
#define NSTAGE 3
#define GEMM_SMEM   (NSTAGE * STAGE_BYTES)    // 98304
#define GEMM_GRID   304              // 2 CTAs/SM * 152 SMs (GB300)

static __device__ __forceinline__ void stage_load(
    uint32_t sbase, int tid,
    const __half* __restrict__ aP, const __half* __restrict__ bP)
{
    const __half* srcs[2] = {aP, bP};
    #pragma unroll
    for (int b = 0; b < 2; b++) {
        const __half* s = srcs[b];
        uint32_t dbase = sbase + b * A_BUF;
        #pragma unroll
        for (int i = 0; i < 4; i++) {
            int id  = tid + i * 256;          // 0..1023 (128 rows x 8 chunks)
            int row = id >> 3, ch = id & 7;
            uint32_t off = SMEM_SWIZZLE_128B((uint32_t)(row * 128 + ch * 16));
            cp_async16(dbase + off, s + (size_t)row * CDIM + ch * 8);
        }
    }
}

template <typename OutT>
__global__ __launch_bounds__(256, 2) void gemm_tc(
    const __half* __restrict__ Ah, const __half* __restrict__ Bh,
    const float* __restrict__ bias, OutT* __restrict__ C,
    int Ntot, int ntiles, int gx)
{
    extern __shared__ __align__(128) char sb[];
    const uint32_t su = smem_to_u32(sb);
    const uint32_t suEnd = su + NSTAGE * STAGE_BYTES;

    const int tid    = threadIdx.x;
    const int wid    = tid >> 5;
    const int lane   = tid & 31;
    const int warp_m = wid & 1;      // 0..1 -> 64-row slab
    const int warp_n = wid >> 1;     // 0..3 -> 32-col slab
    const int nct    = (int)gridDim.x;

    int tile = blockIdx.x;
    if (tile >= ntiles) return;

    // ldmatrix per-lane addressing: swizzle XOR (row&7) applied to the FINAL
    // 16B-chunk index (ch0 + 2*kk) inside the unrolled k loop.
    const int aRow = warp_m * 64 + (lane & 15);
    const int aCh0 = lane >> 4;              // 0,1
    const uint32_t aXor    = (uint32_t)(aRow & 7);
    const uint32_t aRowOff = (uint32_t)aRow * 128;
    const int bRow = warp_n * 32 + (lane & 7) + ((lane >> 4) << 3);
    const int bCh0 = (lane >> 3) & 1;        // 0,1
    const uint32_t bXor    = (uint32_t)(bRow & 7);
    const uint32_t bRowOff = (uint32_t)bRow * 128;

    // Div-free tile walk: (trow, tcol) with per-step (dr, dc) carry update.
    int trow = tile / gx;                     // one division total
    int tcol = tile - trow * gx;
    const int dr = nct / gx;
    const int dc = nct - dr * gx;

    const __half* aT = Ah + (size_t)trow * BM * CDIM;
    const __half* bT = Bh + (size_t)tcol * BN * CDIM;

    // Prologue: issue chunks 0,1 of the first tile.
    stage_load(su, tid, aT, bT);
    cp_commit();
    stage_load(su + STAGE_BYTES, tid, aT + KT, bT + KT);
    cp_commit();

    uint32_t sC = su;                          // compute stage (chunk t)
    uint32_t sI = su + 2 * STAGE_BYTES;        // issue stage  (chunk t+2)

    for (;;) {
        // Next tile coords (carry update, no div).
        int nrow = trow + dr, ncol = tcol + dc;
        if (ncol >= gx) { ncol -= gx; nrow += 1; }
        const bool hasNext = (tile + nct) < ntiles;
        const __half* naT = Ah + (size_t)nrow * BM * CDIM;
        const __half* nbT = Bh + (size_t)ncol * BN * CDIM;

        float acc[4][4][4];
        #pragma unroll
        for (int mi = 0; mi < 4; mi++)
            #pragma unroll
            for (int ni = 0; ni < 4; ni++)
                #pragma unroll
                for (int j = 0; j < 4; j++) acc[mi][ni][j] = 0.0f;

        #pragma unroll
        for (int t = 0; t < 4; t++) {
            // Chunk t landed (groups retire in order; one commit per chunk).
            if (t == 3) { if (hasNext) cp_wait<1>(); else cp_wait<0>(); }
            else        cp_wait<1>();
            __syncthreads();   // also: everyone done reading stage sI's prior data

            // Issue chunk t+2 into sI (current tile k=t+2, or next tile k=t-2).
            if (t < 2) {
                stage_load(sI, tid, aT + (t + 2) * KT, bT + (t + 2) * KT);
                cp_commit();
            } else if (hasNext) {
                stage_load(sI, tid, naT + (t - 2) * KT, nbT + (t - 2) * KT);
                cp_commit();
            }

            // Compute chunk t from sC.
            #pragma unroll
            for (int kk = 0; kk < 4; kk++) {   // k16 steps within chunk
                const uint32_t aOff =
                    aRowOff + ((((uint32_t)(aCh0 + 2 * kk)) ^ aXor) << 4);
                const uint32_t bOff =
                    bRowOff + ((((uint32_t)(bCh0 + 2 * kk)) ^ bXor) << 4);
                uint32_t ah[4][4];
                #pragma unroll
                for (int mi = 0; mi < 4; mi++)
                    ldmx4(ah[mi], sC + aOff + mi * 2048);
                #pragma unroll
                for (int g = 0; g < 2; g++) {  // n16 groups
                    uint32_t bh[4];
                    ldmx4(bh, sC + A_BUF + bOff + g * 2048);
                    #pragma unroll
                    for (int ni2 = 0; ni2 < 2; ni2++) {
                        const int ni = g * 2 + ni2;
                        const int p  = ni2 * 2;
                        #pragma unroll
                        for (int mi = 0; mi < 4; mi++)
                            mma_f16(acc[mi][ni], ah[mi], bh[p], bh[p + 1]);
                    }
                }
            }

            sC += STAGE_BYTES; if (sC == suEnd) sC = su;
            sI += STAGE_BYTES; if (sI == suEnd) sI = su;
        }

        // Epilogue for this tile (overlaps next tile's in-flight chunk loads).
        {
            const int brow = trow * BM, bcol = tcol * BN;
            #pragma unroll
            for (int mi = 0; mi < 4; mi++) {
                const int r0 = brow + warp_m * 64 + mi * 16 + (lane >> 2);
                #pragma unroll
                for (int ni = 0; ni < 4; ni++) {
                    const int col = bcol + warp_n * 32 + ni * 8 + (lane & 3) * 2;
                    const float b0 = bias[col], b1 = bias[col + 1];
                    if constexpr (sizeof(OutT) == 2) {
                        __half2 v0 = __floats2half2_rn(acc[mi][ni][0] + b0,
                                                       acc[mi][ni][1] + b1);
                        __half2 v1 = __floats2half2_rn(acc[mi][ni][2] + b0,
                                                       acc[mi][ni][3] + b1);
                        *reinterpret_cast<__half2*>(
                            &C[(size_t)r0 * Ntot + col]) = v0;
                        *reinterpret_cast<__half2*>(
                            &C[(size_t)(r0 + 8) * Ntot + col]) = v1;
                    } else {
                        float2 v0 = {acc[mi][ni][0] + b0, acc[mi][ni][1] + b1};
                        float2 v1 = {acc[mi][ni][2] + b0, acc[mi][ni][3] + b1};
                        *reinterpret_cast<float2*>(
                            &C[(size_t)r0 * Ntot + col]) = v0;
                        *reinterpret_cast<float2*>(
                            &C[(size_t)(r0 + 8) * Ntot + col]) = v1;
                    }
                }
            }
        }

        if (!hasNext) break;
        trow = nrow; tcol = ncol; aT = naT; bT = nbT; tile += nct;
    }
}

// ---------------------------------------------------------------------------
// Windowed causal attention: one warp per (window, head), half2 I/O.
// Lane l holds head-dims {2l, 2l+1}. Reads fp16 qkv, writes fp16 att.
// ---------------------------------------------------------------------------
#define QKV2 (QKVDIM / 2)   // 384 half2 per token
#define C2   (CDIM / 2)     // 128 half2 per token
#define HD2  (HDIM / 2)     // 32 half2 per head

__global__ __launch_bounds__(256) void attn_window_kernel(
    const __half2* __restrict__ qkv2, __half2* __restrict__ out2)
{
    const int warp_global = blockIdx.x * 8 + (threadIdx.x >> 5);
    const int lane = threadIdx.x & 31;
    const int win  = warp_global >> 2;
    const int head = warp_global & 3;
    const float scale = 0.125f;

    const __half2* base = qkv2 + (size_t)win * 8 * QKV2 + head * HD2 + lane;

    float2 q[8], k[8], v[8];
    #pragma unroll
    for (int i = 0; i < 8; i++) {
        q[i] = __half22float2(base[i * QKV2]);
        k[i] = __half22float2(base[i * QKV2 + 128]);   // +256 dims
        v[i] = __half22float2(base[i * QKV2 + 256]);   // +512 dims
    }

    float p[8][8];
    #pragma unroll
    for (int i = 0; i < 8; i++) {
        #pragma unroll
        for (int j = 0; j < 8; j++) {
            float s = q[i].x * k[j].x + q[i].y * k[j].y;
            #pragma unroll
            for (int o = 16; o > 0; o >>= 1)
                s += __shfl_xor_sync(0xffffffffu, s, o);
            p[i][j] = s * scale;
        }
    }

    #pragma unroll
    for (int i = 0; i < 8; i++) {
        float mx = p[i][0];
        #pragma unroll
        for (int j = 1; j < 8; j++)
            if (j <= i) mx = fmaxf(mx, p[i][j]);
        float sum = 0.0f;
        #pragma unroll
        for (int j = 0; j < 8; j++) {
            if (j <= i) { float e = __expf(p[i][j] - mx); p[i][j] = e; sum += e; }
            else          p[i][j] = 0.0f;
        }
        float inv = 1.0f / sum;
        #pragma unroll
        for (int j = 0; j < 8; j++) p[i][j] *= inv;
    }

    __half2* ob = out2 + (size_t)win * 8 * C2 + head * HD2 + lane;
    #pragma unroll
    for (int i = 0; i < 8; i++) {
        float ox = 0.0f, oy = 0.0f;
        #pragma unroll
        for (int j = 0; j < 8; j++) {
            ox = fmaf(p[i][j], v[j].x, ox);
            oy = fmaf(p[i][j], v[j].y, oy);
        }
        ob[i * C2] = __floats2half2_rn(ox, oy);
    }
}

// ---------------------------------------------------------------------------
// Launch
// ---------------------------------------------------------------------------
extern "C" void kernel_launch(void* const* d_in, const int* in_sizes, int n_in,
                              void* d_out, int out_size)
{
    const float* x      = (const float*)d_in[0];
    const float* w_qkv  = (const float*)d_in[1];
    const float* b_qkv  = (const float*)d_in[2];
    const float* w_proj = (const float*)d_in[3];
    const float* b_proj = (const float*)d_in[4];
    float* out = (float*)d_out;

    __half *qkv_buf, *xh, *ath, *wqh, *wph;
    cudaGetSymbolAddress((void**)&qkv_buf, g_qkv);
    cudaGetSymbolAddress((void**)&xh,  g_xh);
    cudaGetSymbolAddress((void**)&ath, g_ath);
    cudaGetSymbolAddress((void**)&wqh, g_wqh);
    cudaGetSymbolAddress((void**)&wph, g_wph);

    cudaFuncSetAttribute(gemm_tc<__half>,
                         cudaFuncAttributeMaxDynamicSharedMemorySize, GEMM_SMEM);
    cudaFuncSetAttribute(gemm_tc<float>,
                         cudaFuncAttributeMaxDynamicSharedMemorySize, GEMM_SMEM);

    // Converts: x, weights -> fp16
    convert_h<<<(TOKENS * CDIM / 4) / 256, 256>>>(x, xh, TOKENS * CDIM / 4);
    convert_h<<<(QKVDIM * CDIM / 4) / 256, 256>>>(w_qkv, wqh, QKVDIM * CDIM / 4);
    convert_h<<<(CDIM * CDIM / 4) / 256, 256>>>(w_proj, wph, CDIM * CDIM / 4);

    // K1: qkv = x @ w_qkv^T + b_qkv   (M=131072, N=768, K=256) -> fp16
    {
        const int gx = QKVDIM / BN;              // 6
        const int ntiles = gx * (TOKENS / BM);   // 6144
        gemm_tc<__half><<<GEMM_GRID, 256, GEMM_SMEM>>>(
            xh, wqh, b_qkv, qkv_buf, QKVDIM, ntiles, gx);
    }

    // K2: windowed causal attention (fp16 in, half2 I/O) -> fp16
    attn_window_kernel<<<(NWIN * NHEAD) / 8, 256>>>(
        (const __half2*)qkv_buf, (__half2*)ath);

    // K3: out = att @ w_proj^T + b_proj  (M=131072, N=256, K=256) -> fp32
    {
        const int gx = CDIM / BN;                // 2
        const int ntiles = gx * (TOKENS / BM);   // 2048
        gemm_tc<float><<<GEMM_GRID, 256, GEMM_SMEM>>>(
            ath, wph, b_proj, out, CDIM, ntiles, gx);
    }
}